// round 3
// baseline (speedup 1.0000x reference)
#include <cuda_runtime.h>

#define GRID_N 160
#define G2 (GRID_N*GRID_N)
#define G3 (GRID_N*GRID_N*GRID_N)
#define NS 256
#define SB 4
#define NT (NS/SB)
#define WIDTH 128
#define ACT_SHIFT (-4.59511985013459f)   /* log(1/99) */
#define NTASK (13*SB*4)                  /* 208 */

__device__ __forceinline__ float sigmoidf_(float x){ return 1.f/(1.f+expf(-x)); }

// Compute gather pointer + interp weights for one (sample, channel, xy-corner) task.
__device__ __forceinline__ void task_prep(
    int task, int tt,
    float ox, float oy, float oz, float dx, float dy, float dz,
    const float* __restrict__ density, const float* __restrict__ k0,
    const float** pp, float* paz, float* pwxy, int* pcc, int* pss)
{
    int ss  = task / 52;
    int rem = task - ss*52;
    int cc  = rem >> 2;
    int corner = rem & 3;
    float t = 0.2f + (float)(tt*SB + ss) * (1.6f/255.0f);
    float gx = fminf(fmaxf((fmaf(dx,t,ox)+1.f)*79.5f, 0.f), 159.f);
    float gy = fminf(fmaxf((fmaf(dy,t,oy)+1.f)*79.5f, 0.f), 159.f);
    float gz = fminf(fmaxf((fmaf(dz,t,oz)+1.f)*79.5f, 0.f), 159.f);
    int x0 = min((int)gx, 158);
    int y0 = min((int)gy, 158);
    int z0 = min((int)gz, 158);
    float ax = gx-(float)x0, ay = gy-(float)y0, az = gz-(float)z0;
    int cx = corner & 1, cy = corner >> 1;
    const float* gp = (cc < 12) ? (k0 + cc*G3) : density;
    *pp   = gp + ((x0+cx)*G2 + (y0+cy)*GRID_N + z0);
    *paz  = az;
    *pwxy = (cx ? ax : 1.f-ax) * (cy ? ay : 1.f-ay);
    *pcc  = cc;
    *pss  = ss;
}

__global__ __launch_bounds__(128, 2)
void dvgo_fused(const float* __restrict__ rays_o, const float* __restrict__ rays_d,
                const float* __restrict__ density, const float* __restrict__ k0,
                const float* __restrict__ W0, const float* __restrict__ b0,
                const float* __restrict__ W1, const float* __restrict__ b1,
                const float* __restrict__ W2, const float* __restrict__ b2,
                float* __restrict__ out)
{
    __shared__ __align__(16) float feats[13*SB];       // [c][s], c==12 -> sigma
    __shared__ __align__(16) float h0s[SB][WIDTH+4];
    __shared__ __align__(16) float h1s[SB][WIDTH+4];
    __shared__ float wsm[SB];
    __shared__ float W2s[WIDTH*3];
    __shared__ float b2s[3];
    __shared__ float accw[4][3];
    __shared__ float alphainv_s;

    const int r    = blockIdx.x;
    const int tid  = threadIdx.x;
    const int lane = tid & 31;
    const int warp = tid >> 5;

    for (int i = tid; i < WIDTH*3; i += 128) W2s[i] = W2[i];
    if (tid < 3) b2s[tid] = b2[tid];

    const float ox = rays_o[3*r+0], oy = rays_o[3*r+1], oz = rays_o[3*r+2];
    const float dx = rays_d[3*r+0], dy = rays_d[3*r+1], dz = rays_d[3*r+2];

    // ---- fold view-embedding part of layer0 into a per-ray constant ----
    float rayterm;
    {
        float inv = rsqrtf(dx*dx + dy*dy + dz*dz);
        float vd[3] = {dx*inv, dy*inv, dz*inv};
        float vemb[27];
        vemb[0]=vd[0]; vemb[1]=vd[1]; vemb[2]=vd[2];
        #pragma unroll
        for (int d=0; d<3; d++){
            #pragma unroll
            for (int k=0; k<4; k++){
                float a = vd[d] * (float)(1<<k);
                vemb[3  + d*4 + k] = sinf(a);
                vemb[15 + d*4 + k] = cosf(a);
            }
        }
        rayterm = b0[tid];
        #pragma unroll
        for (int i=0; i<27; i++)
            rayterm = fmaf(vemb[i], W0[(12+i)*WIDTH + tid], rayterm);
    }

    // ---- resident weight columns ----
    float w0r[12];
    #pragma unroll
    for (int i=0; i<12; i++) w0r[i] = W0[i*WIDTH + tid];
    float w1r[WIDTH];
    #pragma unroll
    for (int i=0; i<WIDTH; i++) w1r[i] = W1[i*WIDTH + tid];
    const float b1r = b1[tid];

    float T = 1.f;                    // thread 0's running transmittance
    float racc0=0.f, racc1=0.f, racc2=0.f;

    for (int tt=0; tt<NT; tt++){
        // ================= sampling: 208 tasks over 128 threads =================
        // Task A (task id = tid, always < 208)
        const float *pA; float azA, wxyA; int ccA, ssA;
        task_prep(tid, tt, ox,oy,oz, dx,dy,dz, density, k0, &pA,&azA,&wxyA,&ccA,&ssA);
        // Task B (task id = tid+128, active only for tid < 80)
        const int taskB = tid + 128;
        const bool actB = taskB < NTASK;
        const float *pB = pA; float azB=0.f, wxyB=0.f; int ccB=0, ssB=0;
        if (actB)
            task_prep(taskB, tt, ox,oy,oz, dx,dy,dz, density, k0, &pB,&azB,&wxyB,&ccB,&ssB);

        // issue all gathers, then combine (MLP=4 in flight)
        float v0A = __ldg(pA), v1A = __ldg(pA+1);
        float v0B = __ldg(pB), v1B = __ldg(pB+1);

        float cA = wxyA * fmaf(azA, v1A - v0A, v0A);
        cA += __shfl_xor_sync(0xffffffffu, cA, 1);
        cA += __shfl_xor_sync(0xffffffffu, cA, 2);
        if ((tid & 3) == 0) feats[ccA*SB + ssA] = cA;

        float cB = actB ? (wxyB * fmaf(azB, v1B - v0B, v0B)) : 0.f;
        cB += __shfl_xor_sync(0xffffffffu, cB, 1);
        cB += __shfl_xor_sync(0xffffffffu, cB, 2);
        if (actB && (taskB & 3) == 0) feats[ccB*SB + ssB] = cB;
        __syncthreads();

        // ================= transmittance scan (thread 0, serial) =================
        if (tid == 0){
            #pragma unroll
            for (int s=0; s<SB; s++){
                float sg = feats[12*SB + s];
                float e  = expf(sg + ACT_SHIFT);
                float a  = 1.f - rsqrtf(1.f + e);     // 1-(1+e)^(-0.5)
                wsm[s]   = a * T;
                T *= (1.f - a + 1e-10f);
            }
            if (tt == NT-1) alphainv_s = T;
        }

        // ================= layer0: 12 -> 128 (thread j = hidden unit j) =========
        float a0[SB];
        #pragma unroll
        for (int s=0; s<SB; s++) a0[s] = rayterm;
        #pragma unroll
        for (int c=0; c<12; c++){
            float4 f = *(const float4*)&feats[c*SB];
            float  w = w0r[c];
            a0[0] = fmaf(f.x, w, a0[0]);
            a0[1] = fmaf(f.y, w, a0[1]);
            a0[2] = fmaf(f.z, w, a0[2]);
            a0[3] = fmaf(f.w, w, a0[3]);
        }
        #pragma unroll
        for (int s=0; s<SB; s++) h0s[s][tid] = fmaxf(a0[s], 0.f);
        __syncthreads();

        // ================= layer1: 128 -> 128, W1 column in registers ===========
        float a1[SB];
        #pragma unroll
        for (int s=0; s<SB; s++) a1[s] = b1r;
        #pragma unroll
        for (int i=0; i<WIDTH; i+=4){
            float4 q0 = *(const float4*)&h0s[0][i];
            float4 q1 = *(const float4*)&h0s[1][i];
            float4 q2 = *(const float4*)&h0s[2][i];
            float4 q3 = *(const float4*)&h0s[3][i];
            a1[0]=fmaf(q0.x,w1r[i],a1[0]); a1[0]=fmaf(q0.y,w1r[i+1],a1[0]);
            a1[0]=fmaf(q0.z,w1r[i+2],a1[0]); a1[0]=fmaf(q0.w,w1r[i+3],a1[0]);
            a1[1]=fmaf(q1.x,w1r[i],a1[1]); a1[1]=fmaf(q1.y,w1r[i+1],a1[1]);
            a1[1]=fmaf(q1.z,w1r[i+2],a1[1]); a1[1]=fmaf(q1.w,w1r[i+3],a1[1]);
            a1[2]=fmaf(q2.x,w1r[i],a1[2]); a1[2]=fmaf(q2.y,w1r[i+1],a1[2]);
            a1[2]=fmaf(q2.z,w1r[i+2],a1[2]); a1[2]=fmaf(q2.w,w1r[i+3],a1[2]);
            a1[3]=fmaf(q3.x,w1r[i],a1[3]); a1[3]=fmaf(q3.y,w1r[i+1],a1[3]);
            a1[3]=fmaf(q3.z,w1r[i+2],a1[3]); a1[3]=fmaf(q3.w,w1r[i+3],a1[3]);
        }
        #pragma unroll
        for (int s=0; s<SB; s++) h1s[s][tid] = fmaxf(a1[s], 0.f);
        __syncthreads();

        // ================= layer2 + compositing: warp s owns sample s ===========
        {
            const int s = warp;
            float p0=0.f, p1=0.f, p2=0.f;
            #pragma unroll
            for (int k=0; k<4; k++){
                int i = lane + 32*k;
                float h = h1s[s][i];
                p0 = fmaf(h, W2s[3*i+0], p0);
                p1 = fmaf(h, W2s[3*i+1], p1);
                p2 = fmaf(h, W2s[3*i+2], p2);
            }
            #pragma unroll
            for (int off=16; off>0; off>>=1){
                p0 += __shfl_down_sync(0xffffffffu, p0, off);
                p1 += __shfl_down_sync(0xffffffffu, p1, off);
                p2 += __shfl_down_sync(0xffffffffu, p2, off);
            }
            if (lane == 0){
                float w = wsm[s];
                racc0 = fmaf(w, sigmoidf_(p0 + b2s[0]), racc0);
                racc1 = fmaf(w, sigmoidf_(p1 + b2s[1]), racc1);
                racc2 = fmaf(w, sigmoidf_(p2 + b2s[2]), racc2);
            }
        }
        // no trailing sync needed: next tile's first __syncthreads orders
        // feats/wsm/h writes against this tile's layer2 reads.
    }

    if (lane == 0){
        accw[warp][0] = racc0; accw[warp][1] = racc1; accw[warp][2] = racc2;
    }
    __syncthreads();
    if (tid < 3){
        out[3*r + tid] = accw[0][tid] + accw[1][tid] + accw[2][tid] + accw[3][tid]
                       + alphainv_s;
    }
}

extern "C" void kernel_launch(void* const* d_in, const int* in_sizes, int n_in,
                              void* d_out, int out_size)
{
    const float* rays_o  = (const float*)d_in[0];
    const float* rays_d  = (const float*)d_in[1];
    const float* density = (const float*)d_in[2];
    const float* k0      = (const float*)d_in[3];
    const float* W0      = (const float*)d_in[4];
    const float* b0      = (const float*)d_in[5];
    const float* W1      = (const float*)d_in[6];
    const float* b1      = (const float*)d_in[7];
    const float* W2      = (const float*)d_in[8];
    const float* b2      = (const float*)d_in[9];
    float* out = (float*)d_out;

    int n_rays = in_sizes[0] / 3;
    dvgo_fused<<<n_rays, 128>>>(rays_o, rays_d, density, k0,
                                W0, b0, W1, b1, W2, b2, out);
}

// round 4
// speedup vs baseline: 1.0147x; 1.0147x over previous
#include <cuda_runtime.h>

#define GRID_N 160
#define G2 (GRID_N*GRID_N)
#define G3 (GRID_N*GRID_N*GRID_N)
#define NS 256
#define SB 4
#define NT (NS/SB)
#define WIDTH 128
#define ACT_SHIFT (-4.59511985013459f)   /* log(1/99) */
#define NTASK (13*SB*4)                  /* 208 */

typedef unsigned long long ull;

// packed f32x2 fma: acc.lo += a.lo*b.lo ; acc.hi += a.hi*b.hi  (same rounding as scalar FFMA)
#define FMA2(acc, a, b) asm("fma.rn.f32x2 %0, %1, %2, %0;" : "+l"(acc) : "l"(a), "l"(b))

__device__ __forceinline__ ull pack2(float lo, float hi){
    ull r; asm("mov.b64 %0, {%1, %2};" : "=l"(r) : "f"(lo), "f"(hi)); return r;
}
__device__ __forceinline__ float hsum2(ull v){
    float lo, hi; asm("mov.b64 {%0, %1}, %2;" : "=f"(lo), "=f"(hi) : "l"(v));
    return lo + hi;
}
__device__ __forceinline__ float sigmoidf_(float x){ return 1.f/(1.f+__expf(-x)); }

// Compute gather pointer + interp weights for one (sample, channel, xy-corner) task.
__device__ __forceinline__ void task_prep(
    int task, int tt,
    float ox, float oy, float oz, float dx, float dy, float dz,
    const float* __restrict__ density, const float* __restrict__ k0,
    const float** pp, float* paz, float* pwxy, int* pcc, int* pss)
{
    int ss  = task / 52;
    int rem = task - ss*52;
    int cc  = rem >> 2;
    int corner = rem & 3;
    float t = 0.2f + (float)(tt*SB + ss) * (1.6f/255.0f);
    float gx = fminf(fmaxf((fmaf(dx,t,ox)+1.f)*79.5f, 0.f), 159.f);
    float gy = fminf(fmaxf((fmaf(dy,t,oy)+1.f)*79.5f, 0.f), 159.f);
    float gz = fminf(fmaxf((fmaf(dz,t,oz)+1.f)*79.5f, 0.f), 159.f);
    int x0 = min((int)gx, 158);
    int y0 = min((int)gy, 158);
    int z0 = min((int)gz, 158);
    float ax = gx-(float)x0, ay = gy-(float)y0, az = gz-(float)z0;
    int cx = corner & 1, cy = corner >> 1;
    const float* gp = (cc < 12) ? (k0 + cc*G3) : density;
    *pp   = gp + ((x0+cx)*G2 + (y0+cy)*GRID_N + z0);
    *paz  = az;
    *pwxy = (cx ? ax : 1.f-ax) * (cy ? ay : 1.f-ay);
    *pcc  = cc;
    *pss  = ss;
}

__global__ __launch_bounds__(128, 2)
void dvgo_fused(const float* __restrict__ rays_o, const float* __restrict__ rays_d,
                const float* __restrict__ density, const float* __restrict__ k0,
                const float* __restrict__ W0, const float* __restrict__ b0,
                const float* __restrict__ W1, const float* __restrict__ b1,
                const float* __restrict__ W2, const float* __restrict__ b2,
                float* __restrict__ out)
{
    __shared__ __align__(16) float feats[SB][16];      // [s][c], c==12 -> sigma, rest pad
    __shared__ __align__(16) float h0s[SB][WIDTH+4];   // row stride 132*4=528B (16B mult)
    __shared__ __align__(16) float h1s[SB][WIDTH+4];
    __shared__ float wsm[SB];
    __shared__ float W2s[WIDTH*3];
    __shared__ float b2s[3];
    __shared__ float accw[4][3];
    __shared__ float alphainv_s;

    const int r    = blockIdx.x;
    const int tid  = threadIdx.x;
    const int lane = tid & 31;
    const int warp = tid >> 5;

    for (int i = tid; i < WIDTH*3; i += 128) W2s[i] = W2[i];
    if (tid < 3) b2s[tid] = b2[tid];

    const float ox = rays_o[3*r+0], oy = rays_o[3*r+1], oz = rays_o[3*r+2];
    const float dx = rays_d[3*r+0], dy = rays_d[3*r+1], dz = rays_d[3*r+2];

    // ---- fold view-embedding part of layer0 into a per-ray constant ----
    float rayterm;
    {
        float inv = rsqrtf(dx*dx + dy*dy + dz*dz);
        float vd[3] = {dx*inv, dy*inv, dz*inv};
        float vemb[27];
        vemb[0]=vd[0]; vemb[1]=vd[1]; vemb[2]=vd[2];
        #pragma unroll
        for (int d=0; d<3; d++){
            #pragma unroll
            for (int k=0; k<4; k++){
                float a = vd[d] * (float)(1<<k);
                vemb[3  + d*4 + k] = sinf(a);
                vemb[15 + d*4 + k] = cosf(a);
            }
        }
        rayterm = b0[tid];
        #pragma unroll
        for (int i=0; i<27; i++)
            rayterm = fmaf(vemb[i], W0[(12+i)*WIDTH + tid], rayterm);
    }

    // ---- resident weight columns, packed along K in f32x2 pairs ----
    ull w0p[6];
    #pragma unroll
    for (int k=0; k<6; k++)
        w0p[k] = pack2(W0[(2*k)*WIDTH + tid], W0[(2*k+1)*WIDTH + tid]);
    ull w1p[64];
    #pragma unroll
    for (int k=0; k<64; k++)
        w1p[k] = pack2(W1[(2*k)*WIDTH + tid], W1[(2*k+1)*WIDTH + tid]);
    const float b1r = b1[tid];

    float T = 1.f;                    // thread 0's running transmittance
    float racc0=0.f, racc1=0.f, racc2=0.f;

    for (int tt=0; tt<NT; tt++){
        // ================= sampling: 208 tasks over 128 threads =================
        const float *pA; float azA, wxyA; int ccA, ssA;
        task_prep(tid, tt, ox,oy,oz, dx,dy,dz, density, k0, &pA,&azA,&wxyA,&ccA,&ssA);
        const int taskB = tid + 128;
        const bool actB = taskB < NTASK;
        const float *pB = pA; float azB=0.f, wxyB=0.f; int ccB=0, ssB=0;
        if (actB)
            task_prep(taskB, tt, ox,oy,oz, dx,dy,dz, density, k0, &pB,&azB,&wxyB,&ccB,&ssB);

        float v0A = __ldg(pA), v1A = __ldg(pA+1);
        float v0B = __ldg(pB), v1B = __ldg(pB+1);

        float cA = wxyA * fmaf(azA, v1A - v0A, v0A);
        cA += __shfl_xor_sync(0xffffffffu, cA, 1);
        cA += __shfl_xor_sync(0xffffffffu, cA, 2);
        if ((tid & 3) == 0) feats[ssA][ccA] = cA;

        float cB = actB ? (wxyB * fmaf(azB, v1B - v0B, v0B)) : 0.f;
        cB += __shfl_xor_sync(0xffffffffu, cB, 1);
        cB += __shfl_xor_sync(0xffffffffu, cB, 2);
        if (actB && (taskB & 3) == 0) feats[ssB][ccB] = cB;
        __syncthreads();

        // ================= transmittance scan (thread 0, serial) =================
        if (tid == 0){
            #pragma unroll
            for (int s=0; s<SB; s++){
                float sg = feats[s][12];
                float e  = __expf(sg + ACT_SHIFT);
                float a  = 1.f - rsqrtf(1.f + e);     // 1-(1+e)^(-0.5)
                wsm[s]   = a * T;
                T *= (1.f - a + 1e-10f);
            }
            if (tt == NT-1) alphainv_s = T;
        }

        // ================= layer0: 12 -> 128 (packed f32x2 over channels) =======
        #pragma unroll
        for (int s=0; s<SB; s++){
            ull acc = pack2(rayterm, 0.f);
            #pragma unroll
            for (int k=0; k<3; k++){
                ulonglong2 f = *(const ulonglong2*)&feats[s][4*k];
                FMA2(acc, f.x, w0p[2*k]);
                FMA2(acc, f.y, w0p[2*k+1]);
            }
            h0s[s][tid] = fmaxf(hsum2(acc), 0.f);
        }
        __syncthreads();

        // ================= layer1: 128 -> 128 (packed f32x2 over K) =============
        {
            ull a1p0 = pack2(b1r, 0.f), a1p1 = pack2(b1r, 0.f);
            ull a1p2 = pack2(b1r, 0.f), a1p3 = pack2(b1r, 0.f);
            #pragma unroll
            for (int i=0; i<WIDTH; i+=4){
                ulonglong2 q0 = *(const ulonglong2*)&h0s[0][i];
                ulonglong2 q1 = *(const ulonglong2*)&h0s[1][i];
                ulonglong2 q2 = *(const ulonglong2*)&h0s[2][i];
                ulonglong2 q3 = *(const ulonglong2*)&h0s[3][i];
                ull wlo = w1p[i/2], whi = w1p[i/2+1];
                FMA2(a1p0, q0.x, wlo); FMA2(a1p0, q0.y, whi);
                FMA2(a1p1, q1.x, wlo); FMA2(a1p1, q1.y, whi);
                FMA2(a1p2, q2.x, wlo); FMA2(a1p2, q2.y, whi);
                FMA2(a1p3, q3.x, wlo); FMA2(a1p3, q3.y, whi);
            }
            h1s[0][tid] = fmaxf(hsum2(a1p0), 0.f);
            h1s[1][tid] = fmaxf(hsum2(a1p1), 0.f);
            h1s[2][tid] = fmaxf(hsum2(a1p2), 0.f);
            h1s[3][tid] = fmaxf(hsum2(a1p3), 0.f);
        }
        __syncthreads();

        // ================= layer2 + compositing: warp s owns sample s ===========
        {
            const int s = warp;
            float p0=0.f, p1=0.f, p2=0.f;
            #pragma unroll
            for (int k=0; k<4; k++){
                int i = lane + 32*k;
                float h = h1s[s][i];
                p0 = fmaf(h, W2s[3*i+0], p0);
                p1 = fmaf(h, W2s[3*i+1], p1);
                p2 = fmaf(h, W2s[3*i+2], p2);
            }
            #pragma unroll
            for (int off=16; off>0; off>>=1){
                p0 += __shfl_down_sync(0xffffffffu, p0, off);
                p1 += __shfl_down_sync(0xffffffffu, p1, off);
                p2 += __shfl_down_sync(0xffffffffu, p2, off);
            }
            if (lane == 0){
                float w = wsm[s];
                racc0 = fmaf(w, sigmoidf_(p0 + b2s[0]), racc0);
                racc1 = fmaf(w, sigmoidf_(p1 + b2s[1]), racc1);
                racc2 = fmaf(w, sigmoidf_(p2 + b2s[2]), racc2);
            }
        }
        // next tile's first __syncthreads orders writes vs this tile's reads
    }

    if (lane == 0){
        accw[warp][0] = racc0; accw[warp][1] = racc1; accw[warp][2] = racc2;
    }
    __syncthreads();
    if (tid < 3){
        out[3*r + tid] = accw[0][tid] + accw[1][tid] + accw[2][tid] + accw[3][tid]
                       + alphainv_s;
    }
}

extern "C" void kernel_launch(void* const* d_in, const int* in_sizes, int n_in,
                              void* d_out, int out_size)
{
    const float* rays_o  = (const float*)d_in[0];
    const float* rays_d  = (const float*)d_in[1];
    const float* density = (const float*)d_in[2];
    const float* k0      = (const float*)d_in[3];
    const float* W0      = (const float*)d_in[4];
    const float* b0      = (const float*)d_in[5];
    const float* W1      = (const float*)d_in[6];
    const float* b1      = (const float*)d_in[7];
    const float* W2      = (const float*)d_in[8];
    const float* b2      = (const float*)d_in[9];
    float* out = (float*)d_out;

    int n_rays = in_sizes[0] / 3;
    dvgo_fused<<<n_rays, 128>>>(rays_o, rays_d, density, k0,
                                W0, b0, W1, b1, W2, b2, out);
}

// round 5
// speedup vs baseline: 1.0170x; 1.0022x over previous
#include <cuda_runtime.h>

#define GRID_N 160
#define G2 (GRID_N*GRID_N)
#define G3 (GRID_N*GRID_N*GRID_N)
#define NS 256
#define SB 4
#define NT (NS/SB)
#define WIDTH 128
#define ACT_SHIFT (-4.59511985013459f)   /* log(1/99) */
#define NTASK (13*SB*4)                  /* 208 */

typedef unsigned long long ull;

// packed f32x2 fma: acc.lo += a.lo*b.lo ; acc.hi += a.hi*b.hi  (same rounding as scalar FFMA)
#define FMA2(acc, a, b) asm("fma.rn.f32x2 %0, %1, %2, %0;" : "+l"(acc) : "l"(a), "l"(b))

__device__ __forceinline__ ull pack2(float lo, float hi){
    ull r; asm("mov.b64 %0, {%1, %2};" : "=l"(r) : "f"(lo), "f"(hi)); return r;
}
__device__ __forceinline__ float hsum2(ull v){
    float lo, hi; asm("mov.b64 {%0, %1}, %2;" : "=f"(lo), "=f"(hi) : "l"(v));
    return lo + hi;
}
__device__ __forceinline__ float sigmoidf_(float x){ return 1.f/(1.f+__expf(-x)); }

// Compute gather pointer + interp weights for one (sample, channel, xy-corner) task.
__device__ __forceinline__ void task_prep(
    int task, int tt,
    float ox, float oy, float oz, float dx, float dy, float dz,
    const float* __restrict__ density, const float* __restrict__ k0,
    const float** pp, float* paz, float* pwxy, int* pcc, int* pss)
{
    int ss  = task / 52;
    int rem = task - ss*52;
    int cc  = rem >> 2;
    int corner = rem & 3;
    float t = 0.2f + (float)(tt*SB + ss) * (1.6f/255.0f);
    float gx = fminf(fmaxf((fmaf(dx,t,ox)+1.f)*79.5f, 0.f), 159.f);
    float gy = fminf(fmaxf((fmaf(dy,t,oy)+1.f)*79.5f, 0.f), 159.f);
    float gz = fminf(fmaxf((fmaf(dz,t,oz)+1.f)*79.5f, 0.f), 159.f);
    int x0 = min((int)gx, 158);
    int y0 = min((int)gy, 158);
    int z0 = min((int)gz, 158);
    float ax = gx-(float)x0, ay = gy-(float)y0, az = gz-(float)z0;
    int cx = corner & 1, cy = corner >> 1;
    const float* gp = (cc < 12) ? (k0 + cc*G3) : density;
    *pp   = gp + ((x0+cx)*G2 + (y0+cy)*GRID_N + z0);
    *paz  = az;
    *pwxy = (cx ? ax : 1.f-ax) * (cy ? ay : 1.f-ay);
    *pcc  = cc;
    *pss  = ss;
}

__global__ __launch_bounds__(128, 2)
void dvgo_fused(const float* __restrict__ rays_o, const float* __restrict__ rays_d,
                const float* __restrict__ density, const float* __restrict__ k0,
                const float* __restrict__ W0, const float* __restrict__ b0,
                const float* __restrict__ W1, const float* __restrict__ b1,
                const float* __restrict__ W2, const float* __restrict__ b2,
                float* __restrict__ out)
{
    __shared__ __align__(16) float feats[SB][16];      // [s][c], c==12 -> sigma, rest pad
    __shared__ __align__(16) float h0s[SB][WIDTH+4];   // row stride 132*4=528B (16B mult)
    __shared__ __align__(16) float h1s[SB][WIDTH+4];
    __shared__ float wsm[SB];
    __shared__ float W2s[WIDTH*3];
    __shared__ float b2s[3];
    __shared__ float accw[4][3];
    __shared__ float alphainv_s;

    const int r    = blockIdx.x;
    const int tid  = threadIdx.x;
    const int lane = tid & 31;
    const int warp = tid >> 5;

    for (int i = tid; i < WIDTH*3; i += 128) W2s[i] = W2[i];
    if (tid < 3) b2s[tid] = b2[tid];

    const float ox = rays_o[3*r+0], oy = rays_o[3*r+1], oz = rays_o[3*r+2];
    const float dx = rays_d[3*r+0], dy = rays_d[3*r+1], dz = rays_d[3*r+2];

    // ---- fold view-embedding part of layer0 into a per-ray constant ----
    float rayterm;
    {
        float inv = rsqrtf(dx*dx + dy*dy + dz*dz);
        float vd[3] = {dx*inv, dy*inv, dz*inv};
        float vemb[27];
        vemb[0]=vd[0]; vemb[1]=vd[1]; vemb[2]=vd[2];
        #pragma unroll
        for (int d=0; d<3; d++){
            #pragma unroll
            for (int k=0; k<4; k++){
                float a = vd[d] * (float)(1<<k);
                vemb[3  + d*4 + k] = sinf(a);
                vemb[15 + d*4 + k] = cosf(a);
            }
        }
        rayterm = b0[tid];
        #pragma unroll
        for (int i=0; i<27; i++)
            rayterm = fmaf(vemb[i], W0[(12+i)*WIDTH + tid], rayterm);
    }

    // ---- resident weight columns, packed along K in f32x2 pairs ----
    ull w0p[6];
    #pragma unroll
    for (int k=0; k<6; k++)
        w0p[k] = pack2(W0[(2*k)*WIDTH + tid], W0[(2*k+1)*WIDTH + tid]);
    ull w1p[64];
    #pragma unroll
    for (int k=0; k<64; k++)
        w1p[k] = pack2(W1[(2*k)*WIDTH + tid], W1[(2*k+1)*WIDTH + tid]);
    const float b1r = b1[tid];

    float T = 1.f;                    // thread 0's running transmittance
    float racc0=0.f, racc1=0.f, racc2=0.f;

    for (int tt=0; tt<NT; tt++){
        // ================= sampling: 208 tasks over 128 threads =================
        const float *pA; float azA, wxyA; int ccA, ssA;
        task_prep(tid, tt, ox,oy,oz, dx,dy,dz, density, k0, &pA,&azA,&wxyA,&ccA,&ssA);
        const int taskB = tid + 128;
        const bool actB = taskB < NTASK;
        const float *pB = pA; float azB=0.f, wxyB=0.f; int ccB=0, ssB=0;
        if (actB)
            task_prep(taskB, tt, ox,oy,oz, dx,dy,dz, density, k0, &pB,&azB,&wxyB,&ccB,&ssB);

        float v0A = __ldg(pA), v1A = __ldg(pA+1);
        float v0B = __ldg(pB), v1B = __ldg(pB+1);

        float cA = wxyA * fmaf(azA, v1A - v0A, v0A);
        cA += __shfl_xor_sync(0xffffffffu, cA, 1);
        cA += __shfl_xor_sync(0xffffffffu, cA, 2);
        if ((tid & 3) == 0) feats[ssA][ccA] = cA;

        float cB = actB ? (wxyB * fmaf(azB, v1B - v0B, v0B)) : 0.f;
        cB += __shfl_xor_sync(0xffffffffu, cB, 1);
        cB += __shfl_xor_sync(0xffffffffu, cB, 2);
        if (actB && (taskB & 3) == 0) feats[ssB][ccB] = cB;
        __syncthreads();

        // ================= transmittance scan (thread 0, serial) =================
        if (tid == 0){
            #pragma unroll
            for (int s=0; s<SB; s++){
                float sg = feats[s][12];
                float e  = __expf(sg + ACT_SHIFT);
                float a  = 1.f - rsqrtf(1.f + e);     // 1-(1+e)^(-0.5)
                wsm[s]   = a * T;
                T *= (1.f - a + 1e-10f);
            }
            if (tt == NT-1) alphainv_s = T;
        }

        // ================= layer0: 12 -> 128 (packed f32x2 over channels) =======
        #pragma unroll
        for (int s=0; s<SB; s++){
            ull acc = pack2(rayterm, 0.f);
            #pragma unroll
            for (int k=0; k<3; k++){
                ulonglong2 f = *(const ulonglong2*)&feats[s][4*k];
                FMA2(acc, f.x, w0p[2*k]);
                FMA2(acc, f.y, w0p[2*k+1]);
            }
            h0s[s][tid] = fmaxf(hsum2(acc), 0.f);
        }
        __syncthreads();

        // ================= layer1: 128 -> 128 (packed f32x2 over K) =============
        {
            ull a1p0 = pack2(b1r, 0.f), a1p1 = pack2(b1r, 0.f);
            ull a1p2 = pack2(b1r, 0.f), a1p3 = pack2(b1r, 0.f);
            #pragma unroll
            for (int i=0; i<WIDTH; i+=4){
                ulonglong2 q0 = *(const ulonglong2*)&h0s[0][i];
                ulonglong2 q1 = *(const ulonglong2*)&h0s[1][i];
                ulonglong2 q2 = *(const ulonglong2*)&h0s[2][i];
                ulonglong2 q3 = *(const ulonglong2*)&h0s[3][i];
                ull wlo = w1p[i/2], whi = w1p[i/2+1];
                FMA2(a1p0, q0.x, wlo); FMA2(a1p0, q0.y, whi);
                FMA2(a1p1, q1.x, wlo); FMA2(a1p1, q1.y, whi);
                FMA2(a1p2, q2.x, wlo); FMA2(a1p2, q2.y, whi);
                FMA2(a1p3, q3.x, wlo); FMA2(a1p3, q3.y, whi);
            }
            h1s[0][tid] = fmaxf(hsum2(a1p0), 0.f);
            h1s[1][tid] = fmaxf(hsum2(a1p1), 0.f);
            h1s[2][tid] = fmaxf(hsum2(a1p2), 0.f);
            h1s[3][tid] = fmaxf(hsum2(a1p3), 0.f);
        }
        __syncthreads();

        // ================= layer2 + compositing: warp s owns sample s ===========
        {
            const int s = warp;
            float p0=0.f, p1=0.f, p2=0.f;
            #pragma unroll
            for (int k=0; k<4; k++){
                int i = lane + 32*k;
                float h = h1s[s][i];
                p0 = fmaf(h, W2s[3*i+0], p0);
                p1 = fmaf(h, W2s[3*i+1], p1);
                p2 = fmaf(h, W2s[3*i+2], p2);
            }
            #pragma unroll
            for (int off=16; off>0; off>>=1){
                p0 += __shfl_down_sync(0xffffffffu, p0, off);
                p1 += __shfl_down_sync(0xffffffffu, p1, off);
                p2 += __shfl_down_sync(0xffffffffu, p2, off);
            }
            if (lane == 0){
                float w = wsm[s];
                racc0 = fmaf(w, sigmoidf_(p0 + b2s[0]), racc0);
                racc1 = fmaf(w, sigmoidf_(p1 + b2s[1]), racc1);
                racc2 = fmaf(w, sigmoidf_(p2 + b2s[2]), racc2);
            }
        }
        // next tile's first __syncthreads orders writes vs this tile's reads
    }

    if (lane == 0){
        accw[warp][0] = racc0; accw[warp][1] = racc1; accw[warp][2] = racc2;
    }
    __syncthreads();
    if (tid < 3){
        out[3*r + tid] = accw[0][tid] + accw[1][tid] + accw[2][tid] + accw[3][tid]
                       + alphainv_s;
    }
}

extern "C" void kernel_launch(void* const* d_in, const int* in_sizes, int n_in,
                              void* d_out, int out_size)
{
    const float* rays_o  = (const float*)d_in[0];
    const float* rays_d  = (const float*)d_in[1];
    const float* density = (const float*)d_in[2];
    const float* k0      = (const float*)d_in[3];
    const float* W0      = (const float*)d_in[4];
    const float* b0      = (const float*)d_in[5];
    const float* W1      = (const float*)d_in[6];
    const float* b1      = (const float*)d_in[7];
    const float* W2      = (const float*)d_in[8];
    const float* b2      = (const float*)d_in[9];
    float* out = (float*)d_out;

    int n_rays = in_sizes[0] / 3;
    dvgo_fused<<<n_rays, 128>>>(rays_o, rays_d, density, k0,
                                W0, b0, W1, b1, W2, b2, out);
}

// round 6
// speedup vs baseline: 1.1433x; 1.1242x over previous
#include <cuda_runtime.h>

#define GRID_N 160
#define G2 (GRID_N*GRID_N)
#define G3 (GRID_N*GRID_N*GRID_N)
#define NS 256
#define SB 4
#define NT (NS/SB)
#define WIDTH 128
#define ACT_SHIFT (-4.59511985013459f)   /* log(1/99) */

typedef unsigned long long ull;

// packed f32x2 fma: acc.lo += a.lo*b.lo ; acc.hi += a.hi*b.hi  (same rounding as scalar FFMA)
#define FMA2(acc, a, b) asm("fma.rn.f32x2 %0, %1, %2, %0;" : "+l"(acc) : "l"(a), "l"(b))

__device__ __forceinline__ ull pack2(float lo, float hi){
    ull r; asm("mov.b64 %0, {%1, %2};" : "=l"(r) : "f"(lo), "f"(hi)); return r;
}
__device__ __forceinline__ float hsum2(ull v){
    float lo, hi; asm("mov.b64 {%0, %1}, %2;" : "=f"(lo), "=f"(hi) : "l"(v));
    return lo + hi;
}
__device__ __forceinline__ float sigmoidf_(float x){ return 1.f/(1.f+__expf(-x)); }

// Channels-last voxel store: [x][y][z][16] floats = 64B/voxel.
// c=0..11: k0 channels, c=12: density, c=13..15: zero pad.
__device__ float g_vox[(size_t)G3 * 16];

__global__ __launch_bounds__(256)
void repack_kernel(const float* __restrict__ density, const float* __restrict__ k0)
{
    int v = blockIdx.x * 256 + threadIdx.x;
    if (v >= G3) return;
    float4 a, b, c, d;
    a.x = k0[0*G3+v];  a.y = k0[1*G3+v];  a.z = k0[2*G3+v];  a.w = k0[3*G3+v];
    b.x = k0[4*G3+v];  b.y = k0[5*G3+v];  b.z = k0[6*G3+v];  b.w = k0[7*G3+v];
    c.x = k0[8*G3+v];  c.y = k0[9*G3+v];  c.z = k0[10*G3+v]; c.w = k0[11*G3+v];
    d.x = density[v];  d.y = 0.f; d.z = 0.f; d.w = 0.f;
    float4* o = (float4*)(g_vox + (size_t)v * 16);
    o[0] = a; o[1] = b; o[2] = c; o[3] = d;
}

__global__ __launch_bounds__(128, 2)
void dvgo_fused(const float* __restrict__ rays_o, const float* __restrict__ rays_d,
                const float* __restrict__ W0, const float* __restrict__ b0,
                const float* __restrict__ W1, const float* __restrict__ b1,
                const float* __restrict__ W2, const float* __restrict__ b2,
                float* __restrict__ out)
{
    __shared__ __align__(16) float feats[SB][16];      // [s][c], c==12 -> sigma
    __shared__ __align__(16) float h0s[SB][WIDTH+4];
    __shared__ __align__(16) float h1s[SB][WIDTH+4];
    __shared__ float wsm[SB];
    __shared__ float W2s[WIDTH*3];
    __shared__ float b2s[3];
    __shared__ float accw[4][3];
    __shared__ float alphainv_s;

    const int r    = blockIdx.x;
    const int tid  = threadIdx.x;
    const int lane = tid & 31;
    const int warp = tid >> 5;

    for (int i = tid; i < WIDTH*3; i += 128) W2s[i] = W2[i];
    if (tid < 3) b2s[tid] = b2[tid];

    const float ox = rays_o[3*r+0], oy = rays_o[3*r+1], oz = rays_o[3*r+2];
    const float dx = rays_d[3*r+0], dy = rays_d[3*r+1], dz = rays_d[3*r+2];

    // ---- fold view-embedding part of layer0 into a per-ray constant ----
    float rayterm;
    {
        float inv = rsqrtf(dx*dx + dy*dy + dz*dz);
        float vd[3] = {dx*inv, dy*inv, dz*inv};
        float vemb[27];
        vemb[0]=vd[0]; vemb[1]=vd[1]; vemb[2]=vd[2];
        #pragma unroll
        for (int d=0; d<3; d++){
            #pragma unroll
            for (int k=0; k<4; k++){
                float a = vd[d] * (float)(1<<k);
                vemb[3  + d*4 + k] = sinf(a);
                vemb[15 + d*4 + k] = cosf(a);
            }
        }
        rayterm = b0[tid];
        #pragma unroll
        for (int i=0; i<27; i++)
            rayterm = fmaf(vemb[i], W0[(12+i)*WIDTH + tid], rayterm);
    }

    // ---- resident weight columns, packed along K in f32x2 pairs ----
    ull w0p[6];
    #pragma unroll
    for (int k=0; k<6; k++)
        w0p[k] = pack2(W0[(2*k)*WIDTH + tid], W0[(2*k+1)*WIDTH + tid]);
    ull w1p[64];
    #pragma unroll
    for (int k=0; k<64; k++)
        w1p[k] = pack2(W1[(2*k)*WIDTH + tid], W1[(2*k+1)*WIDTH + tid]);
    const float b1r = b1[tid];

    // lane decomposition for sampling: lane = corner*4 + chunk
    const int q  = lane & 3;          // float4 chunk (channels 4q..4q+3)
    const int c8 = lane >> 2;         // corner 0..7
    const int cx = (c8 >> 2) & 1, cy = (c8 >> 1) & 1, cz = c8 & 1;

    float T = 1.f;                    // thread 0's running transmittance
    float racc0=0.f, racc1=0.f, racc2=0.f;

    for (int tt=0; tt<NT; tt++){
        // ====== sampling: warp s handles sample s (all 13 channels, 8 corners) ==
        {
            float t = 0.2f + (float)(tt*SB + warp) * (1.6f/255.0f);
            float gx = fminf(fmaxf((fmaf(dx,t,ox)+1.f)*79.5f, 0.f), 159.f);
            float gy = fminf(fmaxf((fmaf(dy,t,oy)+1.f)*79.5f, 0.f), 159.f);
            float gz = fminf(fmaxf((fmaf(dz,t,oz)+1.f)*79.5f, 0.f), 159.f);
            int x0 = min((int)gx, 158);
            int y0 = min((int)gy, 158);
            int z0 = min((int)gz, 158);
            float ax = gx-(float)x0, ay = gy-(float)y0, az = gz-(float)z0;

            size_t vox = (size_t)((x0+cx)*GRID_N + (y0+cy))*GRID_N + (size_t)(z0+cz);
            const float4* p = (const float4*)(g_vox + vox*16) + q;
            float4 v = __ldg(p);
            float wc = (cx ? ax : 1.f-ax) * (cy ? ay : 1.f-ay) * (cz ? az : 1.f-az);
            v.x *= wc; v.y *= wc; v.z *= wc; v.w *= wc;

            #pragma unroll
            for (int off=4; off<32; off<<=1){
                v.x += __shfl_xor_sync(0xffffffffu, v.x, off);
                v.y += __shfl_xor_sync(0xffffffffu, v.y, off);
                v.z += __shfl_xor_sync(0xffffffffu, v.z, off);
                v.w += __shfl_xor_sync(0xffffffffu, v.w, off);
            }
            if (lane < 4) *(float4*)&feats[warp][4*lane] = v;   // lane==q here
        }
        __syncthreads();

        // ================= transmittance scan (thread 0, serial) =================
        if (tid == 0){
            #pragma unroll
            for (int s=0; s<SB; s++){
                float sg = feats[s][12];
                float e  = __expf(sg + ACT_SHIFT);
                float a  = 1.f - rsqrtf(1.f + e);     // 1-(1+e)^(-0.5)
                wsm[s]   = a * T;
                T *= (1.f - a + 1e-10f);
            }
            if (tt == NT-1) alphainv_s = T;
        }

        // ================= layer0: 12 -> 128 (packed f32x2 over channels) =======
        #pragma unroll
        for (int s=0; s<SB; s++){
            ull acc = pack2(rayterm, 0.f);
            #pragma unroll
            for (int k=0; k<3; k++){
                ulonglong2 f = *(const ulonglong2*)&feats[s][4*k];
                FMA2(acc, f.x, w0p[2*k]);
                FMA2(acc, f.y, w0p[2*k+1]);
            }
            h0s[s][tid] = fmaxf(hsum2(acc), 0.f);
        }
        __syncthreads();

        // ================= layer1: 128 -> 128 (packed f32x2 over K) =============
        {
            ull a1p0 = pack2(b1r, 0.f), a1p1 = pack2(b1r, 0.f);
            ull a1p2 = pack2(b1r, 0.f), a1p3 = pack2(b1r, 0.f);
            #pragma unroll
            for (int i=0; i<WIDTH; i+=4){
                ulonglong2 q0 = *(const ulonglong2*)&h0s[0][i];
                ulonglong2 q1 = *(const ulonglong2*)&h0s[1][i];
                ulonglong2 q2 = *(const ulonglong2*)&h0s[2][i];
                ulonglong2 q3 = *(const ulonglong2*)&h0s[3][i];
                ull wlo = w1p[i/2], whi = w1p[i/2+1];
                FMA2(a1p0, q0.x, wlo); FMA2(a1p0, q0.y, whi);
                FMA2(a1p1, q1.x, wlo); FMA2(a1p1, q1.y, whi);
                FMA2(a1p2, q2.x, wlo); FMA2(a1p2, q2.y, whi);
                FMA2(a1p3, q3.x, wlo); FMA2(a1p3, q3.y, whi);
            }
            h1s[0][tid] = fmaxf(hsum2(a1p0), 0.f);
            h1s[1][tid] = fmaxf(hsum2(a1p1), 0.f);
            h1s[2][tid] = fmaxf(hsum2(a1p2), 0.f);
            h1s[3][tid] = fmaxf(hsum2(a1p3), 0.f);
        }
        __syncthreads();

        // ================= layer2 + compositing: warp s owns sample s ===========
        {
            const int s = warp;
            float p0=0.f, p1=0.f, p2=0.f;
            #pragma unroll
            for (int k=0; k<4; k++){
                int i = lane + 32*k;
                float h = h1s[s][i];
                p0 = fmaf(h, W2s[3*i+0], p0);
                p1 = fmaf(h, W2s[3*i+1], p1);
                p2 = fmaf(h, W2s[3*i+2], p2);
            }
            #pragma unroll
            for (int off=16; off>0; off>>=1){
                p0 += __shfl_down_sync(0xffffffffu, p0, off);
                p1 += __shfl_down_sync(0xffffffffu, p1, off);
                p2 += __shfl_down_sync(0xffffffffu, p2, off);
            }
            if (lane == 0){
                float w = wsm[s];
                racc0 = fmaf(w, sigmoidf_(p0 + b2s[0]), racc0);
                racc1 = fmaf(w, sigmoidf_(p1 + b2s[1]), racc1);
                racc2 = fmaf(w, sigmoidf_(p2 + b2s[2]), racc2);
            }
        }
        // next tile's first __syncthreads orders writes vs this tile's reads
    }

    if (lane == 0){
        accw[warp][0] = racc0; accw[warp][1] = racc1; accw[warp][2] = racc2;
    }
    __syncthreads();
    if (tid < 3){
        out[3*r + tid] = accw[0][tid] + accw[1][tid] + accw[2][tid] + accw[3][tid]
                       + alphainv_s;
    }
}

extern "C" void kernel_launch(void* const* d_in, const int* in_sizes, int n_in,
                              void* d_out, int out_size)
{
    const float* rays_o  = (const float*)d_in[0];
    const float* rays_d  = (const float*)d_in[1];
    const float* density = (const float*)d_in[2];
    const float* k0      = (const float*)d_in[3];
    const float* W0      = (const float*)d_in[4];
    const float* b0      = (const float*)d_in[5];
    const float* W1      = (const float*)d_in[6];
    const float* b1      = (const float*)d_in[7];
    const float* W2      = (const float*)d_in[8];
    const float* b2      = (const float*)d_in[9];
    float* out = (float*)d_out;

    repack_kernel<<<(G3 + 255)/256, 256>>>(density, k0);

    int n_rays = in_sizes[0] / 3;
    dvgo_fused<<<n_rays, 128>>>(rays_o, rays_d,
                                W0, b0, W1, b1, W2, b2, out);
}

// round 7
// speedup vs baseline: 1.3794x; 1.2065x over previous
#include <cuda_runtime.h>

#define GRID_N 160
#define G2 (GRID_N*GRID_N)
#define G3 (GRID_N*GRID_N*GRID_N)
#define NS 256
#define SB 8
#define NT (NS/SB)
#define WIDTH 128
#define ACT_SHIFT (-4.59511985013459f)   /* log(1/99) */

typedef unsigned long long ull;

// packed f32x2 fma: acc.lo += a.lo*b.lo ; acc.hi += a.hi*b.hi (same rounding as scalar FFMA)
#define FMA2(acc, a, b) asm("fma.rn.f32x2 %0, %1, %2, %0;" : "+l"(acc) : "l"(a), "l"(b))

__device__ __forceinline__ ull pack2(float lo, float hi){
    ull r; asm("mov.b64 %0, {%1, %2};" : "=l"(r) : "f"(lo), "f"(hi)); return r;
}
__device__ __forceinline__ float hsum2(ull v){
    float lo, hi; asm("mov.b64 {%0, %1}, %2;" : "=f"(lo), "=f"(hi) : "l"(v));
    return lo + hi;
}
__device__ __forceinline__ float sigmoidf_(float x){ return 1.f/(1.f+__expf(-x)); }

// Channels-last voxel store: [x][y][z][16] floats = 64B/voxel.
// c=0..11: k0 channels, c=12: density, c=13..15: zero pad.
__device__ float g_vox[(size_t)G3 * 16];

__global__ __launch_bounds__(256)
void repack_kernel(const float* __restrict__ density, const float* __restrict__ k0)
{
    int v = blockIdx.x * 256 + threadIdx.x;
    if (v >= G3) return;
    float4 a, b, c, d;
    a.x = k0[0*G3+v];  a.y = k0[1*G3+v];  a.z = k0[2*G3+v];  a.w = k0[3*G3+v];
    b.x = k0[4*G3+v];  b.y = k0[5*G3+v];  b.z = k0[6*G3+v];  b.w = k0[7*G3+v];
    c.x = k0[8*G3+v];  c.y = k0[9*G3+v];  c.z = k0[10*G3+v]; c.w = k0[11*G3+v];
    d.x = density[v];  d.y = 0.f; d.z = 0.f; d.w = 0.f;
    float4* o = (float4*)(g_vox + (size_t)v * 16);
    o[0] = a; o[1] = b; o[2] = c; o[3] = d;
}

__global__ __launch_bounds__(256, 2)
void dvgo_fused(const float* __restrict__ rays_o, const float* __restrict__ rays_d,
                const float* __restrict__ W0, const float* __restrict__ b0,
                const float* __restrict__ W1, const float* __restrict__ b1,
                const float* __restrict__ W2, const float* __restrict__ b2,
                float* __restrict__ out)
{
    __shared__ __align__(16) float feats[SB][16];      // [s][c], c==12 -> sigma
    __shared__ __align__(16) float h0s[SB][WIDTH+4];   // row 528B
    __shared__ __align__(16) float part[2][SB][WIDTH]; // layer1 K-half partials
    __shared__ float wsm[SB];
    __shared__ float W2s[WIDTH*3];
    __shared__ float b1sh[WIDTH];
    __shared__ float b2s[3];
    __shared__ float accw[SB][3];
    __shared__ float alphainv_s;

    const int r    = blockIdx.x;
    const int tid  = threadIdx.x;
    const int lane = tid & 31;
    const int warp = tid >> 5;       // 0..7  (sample owner in sampling/layer2)
    const int j    = tid & 127;      // output unit
    const int half = tid >> 7;       // K-half for layer1 / sample-half for layer0

    for (int i = tid; i < WIDTH*3; i += 256) W2s[i] = W2[i];
    if (half == 0) b1sh[j] = b1[j];
    if (tid < 3) b2s[tid] = b2[tid];

    const float ox = rays_o[3*r+0], oy = rays_o[3*r+1], oz = rays_o[3*r+2];
    const float dx = rays_d[3*r+0], dy = rays_d[3*r+1], dz = rays_d[3*r+2];

    // ---- fold view-embedding part of layer0 into a per-ray constant (per unit j) --
    float rayterm;
    {
        float inv = rsqrtf(dx*dx + dy*dy + dz*dz);
        float vd[3] = {dx*inv, dy*inv, dz*inv};
        float vemb[27];
        vemb[0]=vd[0]; vemb[1]=vd[1]; vemb[2]=vd[2];
        #pragma unroll
        for (int d=0; d<3; d++){
            #pragma unroll
            for (int k=0; k<4; k++){
                float a = vd[d] * (float)(1<<k);
                vemb[3  + d*4 + k] = sinf(a);
                vemb[15 + d*4 + k] = cosf(a);
            }
        }
        rayterm = b0[j];
        #pragma unroll
        for (int i=0; i<27; i++)
            rayterm = fmaf(vemb[i], W0[(12+i)*WIDTH + j], rayterm);
    }

    // ---- resident weights: W0 column (all 12), W1 half-column (64 K), packed f32x2 --
    ull w0p[6];
    #pragma unroll
    for (int k=0; k<6; k++)
        w0p[k] = pack2(W0[(2*k)*WIDTH + j], W0[(2*k+1)*WIDTH + j]);
    ull w1p[32];
    #pragma unroll
    for (int k=0; k<32; k++)
        w1p[k] = pack2(W1[(64*half + 2*k)*WIDTH + j],
                       W1[(64*half + 2*k + 1)*WIDTH + j]);

    // lane decomposition for sampling: lane = corner*4 + chunk
    const int q  = lane & 3;          // float4 chunk (channels 4q..4q+3)
    const int c8 = lane >> 2;         // corner 0..7
    const int cx = (c8 >> 2) & 1, cy = (c8 >> 1) & 1, cz = c8 & 1;

    float T = 1.f;                    // thread 0's running transmittance
    float racc0=0.f, racc1=0.f, racc2=0.f;

    for (int tt=0; tt<NT; tt++){
        // ====== sampling: warp s handles sample s (13 channels, 8 corners) ======
        {
            float t = 0.2f + (float)(tt*SB + warp) * (1.6f/255.0f);
            float gx = fminf(fmaxf((fmaf(dx,t,ox)+1.f)*79.5f, 0.f), 159.f);
            float gy = fminf(fmaxf((fmaf(dy,t,oy)+1.f)*79.5f, 0.f), 159.f);
            float gz = fminf(fmaxf((fmaf(dz,t,oz)+1.f)*79.5f, 0.f), 159.f);
            int x0 = min((int)gx, 158);
            int y0 = min((int)gy, 158);
            int z0 = min((int)gz, 158);
            float ax = gx-(float)x0, ay = gy-(float)y0, az = gz-(float)z0;

            size_t vox = (size_t)((x0+cx)*GRID_N + (y0+cy))*GRID_N + (size_t)(z0+cz);
            const float4* p = (const float4*)(g_vox + vox*16) + q;
            float4 v = __ldg(p);
            float wc = (cx ? ax : 1.f-ax) * (cy ? ay : 1.f-ay) * (cz ? az : 1.f-az);
            v.x *= wc; v.y *= wc; v.z *= wc; v.w *= wc;

            #pragma unroll
            for (int off=4; off<32; off<<=1){
                v.x += __shfl_xor_sync(0xffffffffu, v.x, off);
                v.y += __shfl_xor_sync(0xffffffffu, v.y, off);
                v.z += __shfl_xor_sync(0xffffffffu, v.z, off);
                v.w += __shfl_xor_sync(0xffffffffu, v.w, off);
            }
            if (lane < 4) *(float4*)&feats[warp][4*lane] = v;   // lane==q here
        }
        __syncthreads();

        // ============ transmittance scan (thread 0, serial over 8 samples) ======
        if (tid == 0){
            #pragma unroll
            for (int s=0; s<SB; s++){
                float sg = feats[s][12];
                float e  = __expf(sg + ACT_SHIFT);
                float a  = 1.f - rsqrtf(1.f + e);     // 1-(1+e)^(-0.5)
                wsm[s]   = a * T;
                T *= (1.f - a + 1e-10f);
            }
            if (tt == NT-1) alphainv_s = T;
        }

        // ============ layer0: 12 -> 128; half h owns samples 4h..4h+3 ===========
        #pragma unroll
        for (int s4=0; s4<4; s4++){
            const int s = half*4 + s4;
            ull acc = pack2(rayterm, 0.f);
            #pragma unroll
            for (int k=0; k<3; k++){
                ulonglong2 f = *(const ulonglong2*)&feats[s][4*k];
                FMA2(acc, f.x, w0p[2*k]);
                FMA2(acc, f.y, w0p[2*k+1]);
            }
            h0s[s][j] = fmaxf(hsum2(acc), 0.f);
        }
        __syncthreads();

        // ============ layer1: split-K partials over K in [64h, 64h+64) ==========
        #pragma unroll
        for (int sg=0; sg<SB; sg+=4){
            ull a0=0ull, a1=0ull, a2=0ull, a3=0ull;
            #pragma unroll
            for (int i=0; i<64; i+=4){
                const int base = 64*half + i;
                ulonglong2 q0 = *(const ulonglong2*)&h0s[sg+0][base];
                ulonglong2 q1 = *(const ulonglong2*)&h0s[sg+1][base];
                ulonglong2 q2 = *(const ulonglong2*)&h0s[sg+2][base];
                ulonglong2 q3 = *(const ulonglong2*)&h0s[sg+3][base];
                ull wlo = w1p[i/2], whi = w1p[i/2+1];
                FMA2(a0, q0.x, wlo); FMA2(a0, q0.y, whi);
                FMA2(a1, q1.x, wlo); FMA2(a1, q1.y, whi);
                FMA2(a2, q2.x, wlo); FMA2(a2, q2.y, whi);
                FMA2(a3, q3.x, wlo); FMA2(a3, q3.y, whi);
            }
            part[half][sg+0][j] = hsum2(a0);
            part[half][sg+1][j] = hsum2(a1);
            part[half][sg+2][j] = hsum2(a2);
            part[half][sg+3][j] = hsum2(a3);
        }
        __syncthreads();

        // ============ layer2 + compositing: warp s owns sample s ================
        {
            const int s = warp;
            float p0=0.f, p1=0.f, p2=0.f;
            #pragma unroll
            for (int c=0; c<4; c++){
                int k = lane + 32*c;
                float h = fmaxf(b1sh[k] + part[0][s][k] + part[1][s][k], 0.f);
                p0 = fmaf(h, W2s[3*k+0], p0);
                p1 = fmaf(h, W2s[3*k+1], p1);
                p2 = fmaf(h, W2s[3*k+2], p2);
            }
            #pragma unroll
            for (int off=16; off>0; off>>=1){
                p0 += __shfl_down_sync(0xffffffffu, p0, off);
                p1 += __shfl_down_sync(0xffffffffu, p1, off);
                p2 += __shfl_down_sync(0xffffffffu, p2, off);
            }
            if (lane == 0){
                float w = wsm[s];
                racc0 = fmaf(w, sigmoidf_(p0 + b2s[0]), racc0);
                racc1 = fmaf(w, sigmoidf_(p1 + b2s[1]), racc1);
                racc2 = fmaf(w, sigmoidf_(p2 + b2s[2]), racc2);
            }
        }
        // next tile's first __syncthreads orders all rewrites vs these reads
    }

    if (lane == 0){
        accw[warp][0] = racc0; accw[warp][1] = racc1; accw[warp][2] = racc2;
    }
    __syncthreads();
    if (tid < 3){
        float s = alphainv_s;
        #pragma unroll
        for (int w=0; w<SB; w++) s += accw[w][tid];
        out[3*r + tid] = s;
    }
}

extern "C" void kernel_launch(void* const* d_in, const int* in_sizes, int n_in,
                              void* d_out, int out_size)
{
    const float* rays_o  = (const float*)d_in[0];
    const float* rays_d  = (const float*)d_in[1];
    const float* density = (const float*)d_in[2];
    const float* k0      = (const float*)d_in[3];
    const float* W0      = (const float*)d_in[4];
    const float* b0      = (const float*)d_in[5];
    const float* W1      = (const float*)d_in[6];
    const float* b1      = (const float*)d_in[7];
    const float* W2      = (const float*)d_in[8];
    const float* b2      = (const float*)d_in[9];
    float* out = (float*)d_out;

    repack_kernel<<<(G3 + 255)/256, 256>>>(density, k0);

    int n_rays = in_sizes[0] / 3;
    dvgo_fused<<<n_rays, 256>>>(rays_o, rays_d,
                                W0, b0, W1, b1, W2, b2, out);
}

// round 8
// speedup vs baseline: 2.4172x; 1.7524x over previous
#include <cuda_runtime.h>
#include <cuda_bf16.h>

#define GRID_N 160
#define G2 (GRID_N*GRID_N)
#define G3 (GRID_N*GRID_N*GRID_N)
#define NS 256
#define SB 16
#define NT (NS/SB)
#define WIDTH 128
#define ACT_SHIFT (-4.59511985013459f)   /* log(1/99) */

typedef unsigned long long ull;
typedef unsigned int uint;

// packed f32x2 fma: acc.lo += a.lo*b.lo ; acc.hi += a.hi*b.hi (same rounding as scalar FFMA)
#define FMA2(acc, a, b) asm("fma.rn.f32x2 %0, %1, %2, %0;" : "+l"(acc) : "l"(a), "l"(b))

#define MMA_BF16(C, A0,A1,A2,A3, B0,B1) \
    asm volatile("mma.sync.aligned.m16n8k16.row.col.f32.bf16.bf16.f32 " \
        "{%0,%1,%2,%3}, {%4,%5,%6,%7}, {%8,%9}, {%0,%1,%2,%3};" \
        : "+f"((C)[0]),"+f"((C)[1]),"+f"((C)[2]),"+f"((C)[3]) \
        : "r"(A0),"r"(A1),"r"(A2),"r"(A3), "r"(B0),"r"(B1))

#define LDSM_X4(R0,R1,R2,R3, ADDR) \
    asm volatile("ldmatrix.sync.aligned.m8n8.x4.shared.b16 {%0,%1,%2,%3}, [%4];" \
        : "=r"(R0),"=r"(R1),"=r"(R2),"=r"(R3) : "r"(ADDR))

__device__ __forceinline__ ull pack2(float lo, float hi){
    ull r; asm("mov.b64 %0, {%1, %2};" : "=l"(r) : "f"(lo), "f"(hi)); return r;
}
__device__ __forceinline__ float hsum2(ull v){
    float lo, hi; asm("mov.b64 {%0, %1}, %2;" : "=f"(lo), "=f"(hi) : "l"(v));
    return lo + hi;
}
__device__ __forceinline__ float sigmoidf_(float x){ return 1.f/(1.f+__expf(-x)); }

// Channels-last voxel store: [x][y][z][16] floats = 64B/voxel.
__device__ float g_vox[(size_t)G3 * 16];

__global__ __launch_bounds__(256)
void repack_kernel(const float* __restrict__ density, const float* __restrict__ k0)
{
    int v = blockIdx.x * 256 + threadIdx.x;
    if (v >= G3) return;
    float4 a, b, c, d;
    a.x = k0[0*G3+v];  a.y = k0[1*G3+v];  a.z = k0[2*G3+v];  a.w = k0[3*G3+v];
    b.x = k0[4*G3+v];  b.y = k0[5*G3+v];  b.z = k0[6*G3+v];  b.w = k0[7*G3+v];
    c.x = k0[8*G3+v];  c.y = k0[9*G3+v];  c.z = k0[10*G3+v]; c.w = k0[11*G3+v];
    d.x = density[v];  d.y = 0.f; d.z = 0.f; d.w = 0.f;
    float4* o = (float4*)(g_vox + (size_t)v * 16);
    o[0] = a; o[1] = b; o[2] = c; o[3] = d;
}

__global__ __launch_bounds__(256, 2)
void dvgo_fused(const float* __restrict__ rays_o, const float* __restrict__ rays_d,
                const float* __restrict__ W0, const float* __restrict__ b0,
                const float* __restrict__ W1, const float* __restrict__ b1,
                const float* __restrict__ W2, const float* __restrict__ b2,
                float* __restrict__ out)
{
    __shared__ __align__(16) float feats[SB][16];            // [s][c], c==12 -> sigma
    __shared__ __align__(16) __nv_bfloat16 h0hi[SB][136];    // bf16 hi part of h0
    __shared__ __align__(16) __nv_bfloat16 h0lo[SB][136];    // bf16 lo residual
    __shared__ __align__(16) float part[SB][132];            // layer1 out (pre-relu, b1 incl)
    __shared__ float wsm[SB], avs[SB];
    __shared__ float W2s[WIDTH*3];
    __shared__ float b2s[3];
    __shared__ float accw[8][3];
    __shared__ float alphainv_s;

    const int r    = blockIdx.x;
    const int tid  = threadIdx.x;
    const int lane = tid & 31;
    const int warp = tid >> 5;       // 0..7 : sample owner (sampling/layer2), N-slice owner (MMA)
    const int j    = tid & 127;      // hidden unit for layer0
    const int half = tid >> 7;       // sample-half for layer0

    for (int i = tid; i < WIDTH*3; i += 256) W2s[i] = W2[i];
    if (tid < 3) b2s[tid] = b2[tid];

    const float ox = rays_o[3*r+0], oy = rays_o[3*r+1], oz = rays_o[3*r+2];
    const float dx = rays_d[3*r+0], dy = rays_d[3*r+1], dz = rays_d[3*r+2];

    // ---- fold view-embedding part of layer0 into a per-ray constant (per unit j) --
    float rayterm;
    {
        float inv = rsqrtf(dx*dx + dy*dy + dz*dz);
        float vd[3] = {dx*inv, dy*inv, dz*inv};
        float vemb[27];
        vemb[0]=vd[0]; vemb[1]=vd[1]; vemb[2]=vd[2];
        #pragma unroll
        for (int d=0; d<3; d++){
            #pragma unroll
            for (int k=0; k<4; k++){
                float a = vd[d] * (float)(1<<k);
                vemb[3  + d*4 + k] = sinf(a);
                vemb[15 + d*4 + k] = cosf(a);
            }
        }
        rayterm = b0[j];
        #pragma unroll
        for (int i=0; i<27; i++)
            rayterm = fmaf(vemb[i], W0[(12+i)*WIDTH + j], rayterm);
    }

    // ---- W0 column packed f32x2 (layer0 stays exact fp32) ----
    ull w0p[6];
    #pragma unroll
    for (int k=0; k<6; k++)
        w0p[k] = pack2(W0[(2*k)*WIDTH + j], W0[(2*k+1)*WIDTH + j]);

    // ---- W1 as register-resident bf16 MMA B-fragments, hi+lo split ----
    // warp owns N columns [16*warp, 16*warp+16): 2 n-tiles x 8 k-tiles.
    // B frag (k16n8): b_p = { B[16kt+2*m4+8p][n], B[16kt+2*m4+8p+1][n] }, n = 16w+8nt+(lane>>2)
    const int m4 = lane & 3, ncol = lane >> 2;
    uint Bh[8][2][2], Bl[8][2][2];
    float b1v[2][2];
    #pragma unroll
    for (int nt=0; nt<2; nt++){
        const int n = 16*warp + 8*nt + ncol;
        #pragma unroll
        for (int kt=0; kt<8; kt++){
            #pragma unroll
            for (int p=0; p<2; p++){
                int k = 16*kt + 2*m4 + 8*p;
                float wa = W1[k*WIDTH + n];
                float wb = W1[(k+1)*WIDTH + n];
                __nv_bfloat16 ha = __float2bfloat16(wa);
                __nv_bfloat16 hb = __float2bfloat16(wb);
                float la = wa - __bfloat162float(ha);
                float lb = wb - __bfloat162float(hb);
                Bh[kt][nt][p] = (uint)__bfloat16_as_ushort(ha)
                              | ((uint)__bfloat16_as_ushort(hb) << 16);
                Bl[kt][nt][p] = (uint)__bfloat16_as_ushort(__float2bfloat16(la))
                              | ((uint)__bfloat16_as_ushort(__float2bfloat16(lb)) << 16);
            }
        }
        b1v[nt][0] = b1[16*warp + 8*nt + 2*m4];
        b1v[nt][1] = b1[16*warp + 8*nt + 2*m4 + 1];
    }

    // ldmatrix lane addressing for A (m16k16 from h0hi/h0lo): row = lane&15, col-half = lane>>4
    const int arow = lane & 15;
    const uint acol = (uint)(lane >> 4) * 16u;
    const uint hiaddr = (uint)__cvta_generic_to_shared(&h0hi[arow][0]) + acol;
    const uint loaddr = (uint)__cvta_generic_to_shared(&h0lo[arow][0]) + acol;

    // sampling lane decomposition: lane = corner*4 + chunk
    const int q  = lane & 3;
    const int c8 = lane >> 2;
    const int cx = (c8 >> 2) & 1, cy = (c8 >> 1) & 1, cz = c8 & 1;

    float T = 1.f;
    float racc0=0.f, racc1=0.f, racc2=0.f;

    for (int tt=0; tt<NT; tt++){
        // ====== sampling: warp handles samples warp and warp+8 ==================
        #pragma unroll
        for (int rr=0; rr<2; rr++){
            const int s = warp + 8*rr;
            float t = 0.2f + (float)(tt*SB + s) * (1.6f/255.0f);
            float gx = fminf(fmaxf((fmaf(dx,t,ox)+1.f)*79.5f, 0.f), 159.f);
            float gy = fminf(fmaxf((fmaf(dy,t,oy)+1.f)*79.5f, 0.f), 159.f);
            float gz = fminf(fmaxf((fmaf(dz,t,oz)+1.f)*79.5f, 0.f), 159.f);
            int x0 = min((int)gx, 158);
            int y0 = min((int)gy, 158);
            int z0 = min((int)gz, 158);
            float ax = gx-(float)x0, ay = gy-(float)y0, az = gz-(float)z0;

            size_t vox = (size_t)((x0+cx)*GRID_N + (y0+cy))*GRID_N + (size_t)(z0+cz);
            const float4* p = (const float4*)(g_vox + vox*16) + q;
            float4 v = __ldg(p);
            float wc = (cx ? ax : 1.f-ax) * (cy ? ay : 1.f-ay) * (cz ? az : 1.f-az);
            v.x *= wc; v.y *= wc; v.z *= wc; v.w *= wc;

            #pragma unroll
            for (int off=4; off<32; off<<=1){
                v.x += __shfl_xor_sync(0xffffffffu, v.x, off);
                v.y += __shfl_xor_sync(0xffffffffu, v.y, off);
                v.z += __shfl_xor_sync(0xffffffffu, v.z, off);
                v.w += __shfl_xor_sync(0xffffffffu, v.w, off);
            }
            if (lane < 4) *(float4*)&feats[s][4*lane] = v;
        }
        __syncthreads();

        // ============ transmittance: alphas in parallel, short serial chain =====
        if (warp == 0){
            if (lane < SB){
                float e = __expf(feats[lane][12] + ACT_SHIFT);
                avs[lane] = 1.f - rsqrtf(1.f + e);      // 1-(1+e)^(-0.5)
            }
            __syncwarp();
            if (lane == 0){
                #pragma unroll
                for (int s=0; s<SB; s++){
                    float a = avs[s];
                    wsm[s] = a * T;
                    T *= (1.f - a + 1e-10f);
                }
                if (tt == NT-1) alphainv_s = T;
            }
        }

        // ============ layer0 (fp32 exact): half h owns samples 8h..8h+7 =========
        #pragma unroll
        for (int s4=0; s4<8; s4++){
            const int s = 8*half + s4;
            ull acc = pack2(rayterm, 0.f);
            #pragma unroll
            for (int k=0; k<3; k++){
                ulonglong2 f = *(const ulonglong2*)&feats[s][4*k];
                FMA2(acc, f.x, w0p[2*k]);
                FMA2(acc, f.y, w0p[2*k+1]);
            }
            float hv = fmaxf(hsum2(acc), 0.f);
            __nv_bfloat16 hh = __float2bfloat16(hv);
            h0hi[s][j] = hh;
            h0lo[s][j] = __float2bfloat16(hv - __bfloat162float(hh));
        }
        __syncthreads();

        // ============ layer1: bf16 compensated MMA (hi*hi + hi*lo + lo*hi) ======
        {
            float c0[2][4];
            #pragma unroll
            for (int nt=0; nt<2; nt++){
                c0[nt][0]=b1v[nt][0]; c0[nt][1]=b1v[nt][1];
                c0[nt][2]=b1v[nt][0]; c0[nt][3]=b1v[nt][1];
            }
            #pragma unroll
            for (int kt=0; kt<8; kt++){
                uint ah0,ah1,ah2,ah3, al0,al1,al2,al3;
                LDSM_X4(ah0,ah1,ah2,ah3, hiaddr + (uint)kt*32u);
                LDSM_X4(al0,al1,al2,al3, loaddr + (uint)kt*32u);
                #pragma unroll
                for (int nt=0; nt<2; nt++){
                    MMA_BF16(c0[nt], ah0,ah1,ah2,ah3, Bh[kt][nt][0], Bh[kt][nt][1]);
                    MMA_BF16(c0[nt], ah0,ah1,ah2,ah3, Bl[kt][nt][0], Bl[kt][nt][1]);
                    MMA_BF16(c0[nt], al0,al1,al2,al3, Bh[kt][nt][0], Bh[kt][nt][1]);
                }
            }
            const int row = lane >> 2, cp = 2*(lane & 3);
            #pragma unroll
            for (int nt=0; nt<2; nt++){
                const int n0 = 16*warp + 8*nt + cp;
                *(float2*)&part[row][n0]   = make_float2(c0[nt][0], c0[nt][1]);
                *(float2*)&part[row+8][n0] = make_float2(c0[nt][2], c0[nt][3]);
            }
        }
        __syncthreads();

        // ============ layer2 + compositing: warp handles samples warp, warp+8 ===
        #pragma unroll
        for (int rr=0; rr<2; rr++){
            const int s = warp + 8*rr;
            float p0=0.f, p1=0.f, p2=0.f;
            #pragma unroll
            for (int c=0; c<4; c++){
                int k = lane + 32*c;
                float h = fmaxf(part[s][k], 0.f);   // b1 already folded into MMA acc
                p0 = fmaf(h, W2s[3*k+0], p0);
                p1 = fmaf(h, W2s[3*k+1], p1);
                p2 = fmaf(h, W2s[3*k+2], p2);
            }
            #pragma unroll
            for (int off=16; off>0; off>>=1){
                p0 += __shfl_down_sync(0xffffffffu, p0, off);
                p1 += __shfl_down_sync(0xffffffffu, p1, off);
                p2 += __shfl_down_sync(0xffffffffu, p2, off);
            }
            if (lane == 0){
                float w = wsm[s];
                racc0 = fmaf(w, sigmoidf_(p0 + b2s[0]), racc0);
                racc1 = fmaf(w, sigmoidf_(p1 + b2s[1]), racc1);
                racc2 = fmaf(w, sigmoidf_(p2 + b2s[2]), racc2);
            }
        }
        // next tile's first __syncthreads orders all rewrites vs these reads
    }

    if (lane == 0){
        accw[warp][0] = racc0; accw[warp][1] = racc1; accw[warp][2] = racc2;
    }
    __syncthreads();
    if (tid < 3){
        float s = alphainv_s;
        #pragma unroll
        for (int w=0; w<8; w++) s += accw[w][tid];
        out[3*r + tid] = s;
    }
}

extern "C" void kernel_launch(void* const* d_in, const int* in_sizes, int n_in,
                              void* d_out, int out_size)
{
    const float* rays_o  = (const float*)d_in[0];
    const float* rays_d  = (const float*)d_in[1];
    const float* density = (const float*)d_in[2];
    const float* k0      = (const float*)d_in[3];
    const float* W0      = (const float*)d_in[4];
    const float* b0      = (const float*)d_in[5];
    const float* W1      = (const float*)d_in[6];
    const float* b1      = (const float*)d_in[7];
    const float* W2      = (const float*)d_in[8];
    const float* b2      = (const float*)d_in[9];
    float* out = (float*)d_out;

    repack_kernel<<<(G3 + 255)/256, 256>>>(density, k0);

    int n_rays = in_sizes[0] / 3;
    dvgo_fused<<<n_rays, 256>>>(rays_o, rays_d,
                                W0, b0, W1, b1, W2, b2, out);
}

// round 9
// speedup vs baseline: 2.8196x; 1.1665x over previous
#include <cuda_runtime.h>
#include <cuda_bf16.h>

#define GRID_N 160
#define G2 (GRID_N*GRID_N)
#define G3 (GRID_N*GRID_N*GRID_N)
#define NS 256
#define SB 16
#define NT (NS/SB)
#define WIDTH 128
#define ACT_SHIFT (-4.59511985013459f)   /* log(1/99) */

typedef unsigned long long ull;
typedef unsigned int uint;

#define MMA_BF16(C, A0,A1,A2,A3, B0,B1) \
    asm volatile("mma.sync.aligned.m16n8k16.row.col.f32.bf16.bf16.f32 " \
        "{%0,%1,%2,%3}, {%4,%5,%6,%7}, {%8,%9}, {%0,%1,%2,%3};" \
        : "+f"((C)[0]),"+f"((C)[1]),"+f"((C)[2]),"+f"((C)[3]) \
        : "r"(A0),"r"(A1),"r"(A2),"r"(A3), "r"(B0),"r"(B1))

#define LDSM_X4(R0,R1,R2,R3, ADDR) \
    asm volatile("ldmatrix.sync.aligned.m8n8.x4.shared.b16 {%0,%1,%2,%3}, [%4];" \
        : "=r"(R0),"=r"(R1),"=r"(R2),"=r"(R3) : "r"(ADDR))

__device__ __forceinline__ float sigmoidf_(float x){ return 1.f/(1.f+__expf(-x)); }

// split a float into bf16 hi + bf16 lo residual, packed pairwise
__device__ __forceinline__ void split2(float a, float b, uint& hi, uint& lo){
    __nv_bfloat162 h = __floats2bfloat162_rn(a, b);
    float la = a - __bfloat162float(h.x);
    float lb = b - __bfloat162float(h.y);
    __nv_bfloat162 l = __floats2bfloat162_rn(la, lb);
    hi = *(uint*)&h; lo = *(uint*)&l;
}

// Channels-last voxel store: [x][y][z][16] floats = 64B/voxel.
__device__ float g_vox[(size_t)G3 * 16];

__global__ __launch_bounds__(256)
void repack_kernel(const float* __restrict__ density, const float* __restrict__ k0)
{
    int v = blockIdx.x * 256 + threadIdx.x;
    if (v >= G3) return;
    float4 a, b, c, d;
    a.x = k0[0*G3+v];  a.y = k0[1*G3+v];  a.z = k0[2*G3+v];  a.w = k0[3*G3+v];
    b.x = k0[4*G3+v];  b.y = k0[5*G3+v];  b.z = k0[6*G3+v];  b.w = k0[7*G3+v];
    c.x = k0[8*G3+v];  c.y = k0[9*G3+v];  c.z = k0[10*G3+v]; c.w = k0[11*G3+v];
    d.x = density[v];  d.y = 0.f; d.z = 0.f; d.w = 0.f;
    float4* o = (float4*)(g_vox + (size_t)v * 16);
    o[0] = a; o[1] = b; o[2] = c; o[3] = d;
}

__global__ __launch_bounds__(256, 2)
void dvgo_fused(const float* __restrict__ rays_o, const float* __restrict__ rays_d,
                const float* __restrict__ W0, const float* __restrict__ b0,
                const float* __restrict__ W1, const float* __restrict__ b1,
                const float* __restrict__ W2, const float* __restrict__ b2,
                float* __restrict__ out)
{
    __shared__ __align__(16) __nv_bfloat16 fhi[SB][16];      // feats bf16 hi (A tile, k=16)
    __shared__ __align__(16) __nv_bfloat16 flo[SB][16];      // feats bf16 lo
    __shared__ __align__(16) __nv_bfloat16 h0hi[SB][136];    // h0 bf16 hi
    __shared__ __align__(16) __nv_bfloat16 h0lo[SB][136];    // h0 bf16 lo
    __shared__ __align__(16) float part[SB][132];            // layer1 out (pre-relu, b1 incl)
    __shared__ float sigs[SB], wsm[SB], avs[SB];
    __shared__ float rts[WIDTH];                             // rayterm per unit
    __shared__ float W2s[WIDTH*3];
    __shared__ float b2s[3];
    __shared__ float accw[8][3];
    __shared__ float alphainv_s;

    const int r    = blockIdx.x;
    const int tid  = threadIdx.x;
    const int lane = tid & 31;
    const int warp = tid >> 5;       // 0..7 : sample owner (sampling/layer2), N-slice (MMA)
    const int j    = tid & 127;
    const int half = tid >> 7;

    for (int i = tid; i < WIDTH*3; i += 256) W2s[i] = W2[i];
    if (tid < 3) b2s[tid] = b2[tid];

    const float ox = rays_o[3*r+0], oy = rays_o[3*r+1], oz = rays_o[3*r+2];
    const float dx = rays_d[3*r+0], dy = rays_d[3*r+1], dz = rays_d[3*r+2];

    // ---- per-ray constant: b0 + vemb@W0[12:39]  (exact fp32) ----
    {
        float inv = rsqrtf(dx*dx + dy*dy + dz*dz);
        float vd[3] = {dx*inv, dy*inv, dz*inv};
        float vemb[27];
        vemb[0]=vd[0]; vemb[1]=vd[1]; vemb[2]=vd[2];
        #pragma unroll
        for (int d=0; d<3; d++){
            #pragma unroll
            for (int k=0; k<4; k++){
                float a = vd[d] * (float)(1<<k);
                vemb[3  + d*4 + k] = sinf(a);
                vemb[15 + d*4 + k] = cosf(a);
            }
        }
        float rt = b0[j];
        #pragma unroll
        for (int i=0; i<27; i++)
            rt = fmaf(vemb[i], W0[(12+i)*WIDTH + j], rt);
        if (half == 0) rts[j] = rt;
    }

    const int m4 = lane & 3, ncol = lane >> 2;

    // ---- W1 B-fragments (hi+lo bf16), warp owns N cols [16w,16w+16) ----
    uint Bh[8][2][2], Bl[8][2][2];
    float b1v[2][2];
    #pragma unroll
    for (int nt=0; nt<2; nt++){
        const int n = 16*warp + 8*nt + ncol;
        #pragma unroll
        for (int kt=0; kt<8; kt++){
            #pragma unroll
            for (int p=0; p<2; p++){
                int k = 16*kt + 2*m4 + 8*p;
                split2(W1[k*WIDTH + n], W1[(k+1)*WIDTH + n], Bh[kt][nt][p], Bl[kt][nt][p]);
            }
        }
        b1v[nt][0] = b1[16*warp + 8*nt + 2*m4];
        b1v[nt][1] = b1[16*warp + 8*nt + 2*m4 + 1];
    }

    // ---- W0 B-fragments (12 real rows, rows 12..15 zeroed) ----
    uint B0h[2][2], B0l[2][2];
    #pragma unroll
    for (int nt=0; nt<2; nt++){
        const int n = 16*warp + 8*nt + ncol;
        #pragma unroll
        for (int p=0; p<2; p++){
            int k = 2*m4 + 8*p;
            float wa = (k   < 12) ? W0[k*WIDTH + n]     : 0.f;
            float wb = (k+1 < 12) ? W0[(k+1)*WIDTH + n] : 0.f;
            split2(wa, wb, B0h[nt][p], B0l[nt][p]);
        }
    }

    __syncthreads();
    // rayterm accumulator-init values for this warp's columns
    float rt0[2], rt1[2];
    #pragma unroll
    for (int nt=0; nt<2; nt++){
        rt0[nt] = rts[16*warp + 8*nt + 2*m4];
        rt1[nt] = rts[16*warp + 8*nt + 2*m4 + 1];
    }

    // ldmatrix addresses
    const uint fhiaddr = (uint)__cvta_generic_to_shared(&fhi[lane & 15][0]) + (uint)(lane >> 4)*16u;
    const uint floaddr = (uint)__cvta_generic_to_shared(&flo[lane & 15][0]) + (uint)(lane >> 4)*16u;
    const uint hiaddr  = (uint)__cvta_generic_to_shared(&h0hi[lane & 15][0]) + (uint)(lane >> 4)*16u;
    const uint loaddr  = (uint)__cvta_generic_to_shared(&h0lo[lane & 15][0]) + (uint)(lane >> 4)*16u;

    // sampling lane decomposition: lane = corner*4 + chunk
    const int q  = lane & 3;
    const int c8 = lane >> 2;
    const int cx = (c8 >> 2) & 1, cy = (c8 >> 1) & 1, cz = c8 & 1;

    float T = 1.f;
    float racc0=0.f, racc1=0.f, racc2=0.f;

    // ---- prefetch tile 0 gathers ----
    float4 pv[2]; float pw[2];
    #pragma unroll
    for (int rr=0; rr<2; rr++){
        const int s = warp + 8*rr;
        float t = 0.2f + (float)(s) * (1.6f/255.0f);
        float gx = fminf(fmaxf((fmaf(dx,t,ox)+1.f)*79.5f, 0.f), 159.f);
        float gy = fminf(fmaxf((fmaf(dy,t,oy)+1.f)*79.5f, 0.f), 159.f);
        float gz = fminf(fmaxf((fmaf(dz,t,oz)+1.f)*79.5f, 0.f), 159.f);
        int x0 = min((int)gx, 158), y0 = min((int)gy, 158), z0 = min((int)gz, 158);
        float ax = gx-(float)x0, ay = gy-(float)y0, az = gz-(float)z0;
        size_t vox = (size_t)((x0+cx)*GRID_N + (y0+cy))*GRID_N + (size_t)(z0+cz);
        pv[rr] = __ldg((const float4*)(g_vox + vox*16) + q);
        pw[rr] = (cx ? ax : 1.f-ax) * (cy ? ay : 1.f-ay) * (cz ? az : 1.f-az);
    }

    for (int tt=0; tt<NT; tt++){
        // ====== consume prefetched gathers: reduce + write bf16 A tile ========
        #pragma unroll
        for (int rr=0; rr<2; rr++){
            const int s = warp + 8*rr;
            float4 v = pv[rr];
            float wc = pw[rr];
            v.x *= wc; v.y *= wc; v.z *= wc; v.w *= wc;
            #pragma unroll
            for (int off=4; off<32; off<<=1){
                v.x += __shfl_xor_sync(0xffffffffu, v.x, off);
                v.y += __shfl_xor_sync(0xffffffffu, v.y, off);
                v.z += __shfl_xor_sync(0xffffffffu, v.z, off);
                v.w += __shfl_xor_sync(0xffffffffu, v.w, off);
            }
            if (lane < 4){
                uint h01, l01, h23, l23;
                split2(v.x, v.y, h01, l01);
                split2(v.z, v.w, h23, l23);
                *(uint2*)&fhi[s][4*lane] = make_uint2(h01, h23);
                *(uint2*)&flo[s][4*lane] = make_uint2(l01, l23);
            }
            if (lane == 3) sigs[s] = v.x;    // channel 12 = sigma (exact fp32)
        }
        // ====== prefetch next tile (latency hides behind layer0+layer1) ======
        if (tt+1 < NT){
            #pragma unroll
            for (int rr=0; rr<2; rr++){
                const int s = warp + 8*rr;
                float t = 0.2f + (float)((tt+1)*SB + s) * (1.6f/255.0f);
                float gx = fminf(fmaxf((fmaf(dx,t,ox)+1.f)*79.5f, 0.f), 159.f);
                float gy = fminf(fmaxf((fmaf(dy,t,oy)+1.f)*79.5f, 0.f), 159.f);
                float gz = fminf(fmaxf((fmaf(dz,t,oz)+1.f)*79.5f, 0.f), 159.f);
                int x0 = min((int)gx, 158), y0 = min((int)gy, 158), z0 = min((int)gz, 158);
                float ax = gx-(float)x0, ay = gy-(float)y0, az = gz-(float)z0;
                size_t vox = (size_t)((x0+cx)*GRID_N + (y0+cy))*GRID_N + (size_t)(z0+cz);
                pv[rr] = __ldg((const float4*)(g_vox + vox*16) + q);
                pw[rr] = (cx ? ax : 1.f-ax) * (cy ? ay : 1.f-ay) * (cz ? az : 1.f-az);
            }
        }
        __syncthreads();

        // ============ transmittance (warp 0) =================================
        if (warp == 0){
            if (lane < SB){
                float e = __expf(sigs[lane] + ACT_SHIFT);
                avs[lane] = 1.f - rsqrtf(1.f + e);
            }
            __syncwarp();
            if (lane == 0){
                #pragma unroll
                for (int s=0; s<SB; s++){
                    float a = avs[s];
                    wsm[s] = a * T;
                    T *= (1.f - a + 1e-10f);
                }
                if (tt == NT-1) alphainv_s = T;
            }
        }

        // ============ layer0: compensated bf16 MMA, rayterm as C init ========
        {
            float c[2][4];
            #pragma unroll
            for (int nt=0; nt<2; nt++){
                c[nt][0]=rt0[nt]; c[nt][1]=rt1[nt];
                c[nt][2]=rt0[nt]; c[nt][3]=rt1[nt];
            }
            uint ah0,ah1,ah2,ah3, al0,al1,al2,al3;
            LDSM_X4(ah0,ah1,ah2,ah3, fhiaddr);
            LDSM_X4(al0,al1,al2,al3, floaddr);
            #pragma unroll
            for (int nt=0; nt<2; nt++){
                MMA_BF16(c[nt], ah0,ah1,ah2,ah3, B0h[nt][0], B0h[nt][1]);
                MMA_BF16(c[nt], ah0,ah1,ah2,ah3, B0l[nt][0], B0l[nt][1]);
                MMA_BF16(c[nt], al0,al1,al2,al3, B0h[nt][0], B0h[nt][1]);
            }
            // epilogue: relu -> bf16 hi/lo -> h0 tiles (C layout == layer1 A rows)
            const int row = lane >> 2;
            #pragma unroll
            for (int nt=0; nt<2; nt++){
                const int n0 = 16*warp + 8*nt + 2*m4;
                #pragma unroll
                for (int g=0; g<2; g++){
                    float a = fmaxf(c[nt][2*g+0], 0.f);
                    float b = fmaxf(c[nt][2*g+1], 0.f);
                    uint hp, lp;
                    split2(a, b, hp, lp);
                    *(uint*)&h0hi[row + 8*g][n0] = hp;
                    *(uint*)&h0lo[row + 8*g][n0] = lp;
                }
            }
        }
        __syncthreads();

        // ============ layer1: compensated bf16 MMA ===========================
        {
            float c0[2][4];
            #pragma unroll
            for (int nt=0; nt<2; nt++){
                c0[nt][0]=b1v[nt][0]; c0[nt][1]=b1v[nt][1];
                c0[nt][2]=b1v[nt][0]; c0[nt][3]=b1v[nt][1];
            }
            #pragma unroll
            for (int kt=0; kt<8; kt++){
                uint ah0,ah1,ah2,ah3, al0,al1,al2,al3;
                LDSM_X4(ah0,ah1,ah2,ah3, hiaddr + (uint)kt*32u);
                LDSM_X4(al0,al1,al2,al3, loaddr + (uint)kt*32u);
                #pragma unroll
                for (int nt=0; nt<2; nt++){
                    MMA_BF16(c0[nt], ah0,ah1,ah2,ah3, Bh[kt][nt][0], Bh[kt][nt][1]);
                    MMA_BF16(c0[nt], ah0,ah1,ah2,ah3, Bl[kt][nt][0], Bl[kt][nt][1]);
                    MMA_BF16(c0[nt], al0,al1,al2,al3, Bh[kt][nt][0], Bh[kt][nt][1]);
                }
            }
            const int row = lane >> 2, cp = 2*(lane & 3);
            #pragma unroll
            for (int nt=0; nt<2; nt++){
                const int n0 = 16*warp + 8*nt + cp;
                *(float2*)&part[row][n0]   = make_float2(c0[nt][0], c0[nt][1]);
                *(float2*)&part[row+8][n0] = make_float2(c0[nt][2], c0[nt][3]);
            }
        }
        __syncthreads();

        // ============ layer2 + compositing: warp handles samples warp, warp+8 =
        #pragma unroll
        for (int rr=0; rr<2; rr++){
            const int s = warp + 8*rr;
            float p0=0.f, p1=0.f, p2=0.f;
            #pragma unroll
            for (int c=0; c<4; c++){
                int k = lane + 32*c;
                float h = fmaxf(part[s][k], 0.f);
                p0 = fmaf(h, W2s[3*k+0], p0);
                p1 = fmaf(h, W2s[3*k+1], p1);
                p2 = fmaf(h, W2s[3*k+2], p2);
            }
            #pragma unroll
            for (int off=16; off>0; off>>=1){
                p0 += __shfl_down_sync(0xffffffffu, p0, off);
                p1 += __shfl_down_sync(0xffffffffu, p1, off);
                p2 += __shfl_down_sync(0xffffffffu, p2, off);
            }
            if (lane == 0){
                float w = wsm[s];
                racc0 = fmaf(w, sigmoidf_(p0 + b2s[0]), racc0);
                racc1 = fmaf(w, sigmoidf_(p1 + b2s[1]), racc1);
                racc2 = fmaf(w, sigmoidf_(p2 + b2s[2]), racc2);
            }
        }
        // next tile's first __syncthreads orders all rewrites vs these reads
    }

    if (lane == 0){
        accw[warp][0] = racc0; accw[warp][1] = racc1; accw[warp][2] = racc2;
    }
    __syncthreads();
    if (tid < 3){
        float s = alphainv_s;
        #pragma unroll
        for (int w=0; w<8; w++) s += accw[w][tid];
        out[3*r + tid] = s;
    }
}

extern "C" void kernel_launch(void* const* d_in, const int* in_sizes, int n_in,
                              void* d_out, int out_size)
{
    const float* rays_o  = (const float*)d_in[0];
    const float* rays_d  = (const float*)d_in[1];
    const float* density = (const float*)d_in[2];
    const float* k0      = (const float*)d_in[3];
    const float* W0      = (const float*)d_in[4];
    const float* b0      = (const float*)d_in[5];
    const float* W1      = (const float*)d_in[6];
    const float* b1      = (const float*)d_in[7];
    const float* W2      = (const float*)d_in[8];
    const float* b2      = (const float*)d_in[9];
    float* out = (float*)d_out;

    repack_kernel<<<(G3 + 255)/256, 256>>>(density, k0);

    int n_rays = in_sizes[0] / 3;
    dvgo_fused<<<n_rays, 256>>>(rays_o, rays_d,
                                W0, b0, W1, b1, W2, b2, out);
}

// round 10
// speedup vs baseline: 3.8459x; 1.3640x over previous
#include <cuda_runtime.h>
#include <cuda_fp16.h>

#define GRID_N 160
#define G2 (GRID_N*GRID_N)
#define G3 (GRID_N*GRID_N*GRID_N)
#define NS 256
#define SB 16
#define NT (NS/SB)
#define WIDTH 128
#define ACT_SHIFT (-4.59511985013459f)   /* log(1/99) */

typedef unsigned int uint;

#define MMA_F16(C, A0,A1,A2,A3, B0,B1) \
    asm volatile("mma.sync.aligned.m16n8k16.row.col.f32.f16.f16.f32 " \
        "{%0,%1,%2,%3}, {%4,%5,%6,%7}, {%8,%9}, {%0,%1,%2,%3};" \
        : "+f"((C)[0]),"+f"((C)[1]),"+f"((C)[2]),"+f"((C)[3]) \
        : "r"(A0),"r"(A1),"r"(A2),"r"(A3), "r"(B0),"r"(B1))

#define LDSM_X4(R0,R1,R2,R3, ADDR) \
    asm volatile("ldmatrix.sync.aligned.m8n8.x4.shared.b16 {%0,%1,%2,%3}, [%4];" \
        : "=r"(R0),"=r"(R1),"=r"(R2),"=r"(R3) : "r"(ADDR))

__device__ __forceinline__ float sigmoidf_(float x){ return 1.f/(1.f+__expf(-x)); }

__device__ __forceinline__ uint packh2(float a, float b){
    __half2 h = __floats2half2_rn(a, b);
    return *(uint*)&h;
}

// Channels-last voxel store: [x][y][z][16] floats = 64B/voxel.
__device__ float g_vox[(size_t)G3 * 16];

__global__ __launch_bounds__(256)
void repack_kernel(const float* __restrict__ density, const float* __restrict__ k0)
{
    int v = blockIdx.x * 256 + threadIdx.x;
    if (v >= G3) return;
    float4 a, b, c, d;
    a.x = k0[0*G3+v];  a.y = k0[1*G3+v];  a.z = k0[2*G3+v];  a.w = k0[3*G3+v];
    b.x = k0[4*G3+v];  b.y = k0[5*G3+v];  b.z = k0[6*G3+v];  b.w = k0[7*G3+v];
    c.x = k0[8*G3+v];  c.y = k0[9*G3+v];  c.z = k0[10*G3+v]; c.w = k0[11*G3+v];
    d.x = density[v];  d.y = 0.f; d.z = 0.f; d.w = 0.f;
    float4* o = (float4*)(g_vox + (size_t)v * 16);
    o[0] = a; o[1] = b; o[2] = c; o[3] = d;
}

__global__ __launch_bounds__(256, 3)
void dvgo_fused(const float* __restrict__ rays_o, const float* __restrict__ rays_d,
                const float* __restrict__ W0, const float* __restrict__ b0,
                const float* __restrict__ W1, const float* __restrict__ b1,
                const float* __restrict__ W2, const float* __restrict__ b2,
                float* __restrict__ out)
{
    __shared__ __align__(16) __half fth[SB][16];     // feats fp16 (A tile, k=16)
    __shared__ __align__(16) __half h0s[SB][136];    // h0 fp16
    __shared__ __align__(16) float part[SB][132];    // layer1 out (pre-relu, b1 incl)
    __shared__ float sigs[SB], wsm[SB], avs[SB];
    __shared__ float rts[WIDTH];                     // rayterm per unit
    __shared__ float W2s[WIDTH*3];
    __shared__ float b2s[3];
    __shared__ float accw[8][3];
    __shared__ float alphainv_s;

    const int r    = blockIdx.x;
    const int tid  = threadIdx.x;
    const int lane = tid & 31;
    const int warp = tid >> 5;       // 0..7 : sample owner (sampling/layer2), N-slice (MMA)
    const int j    = tid & 127;
    const int half = tid >> 7;

    for (int i = tid; i < WIDTH*3; i += 256) W2s[i] = W2[i];
    if (tid < 3) b2s[tid] = b2[tid];

    const float ox = rays_o[3*r+0], oy = rays_o[3*r+1], oz = rays_o[3*r+2];
    const float dx = rays_d[3*r+0], dy = rays_d[3*r+1], dz = rays_d[3*r+2];

    // ---- per-ray constant: b0 + vemb@W0[12:39]  (exact fp32) ----
    {
        float inv = rsqrtf(dx*dx + dy*dy + dz*dz);
        float vd[3] = {dx*inv, dy*inv, dz*inv};
        float vemb[27];
        vemb[0]=vd[0]; vemb[1]=vd[1]; vemb[2]=vd[2];
        #pragma unroll
        for (int d=0; d<3; d++){
            #pragma unroll
            for (int k=0; k<4; k++){
                float a = vd[d] * (float)(1<<k);
                vemb[3  + d*4 + k] = sinf(a);
                vemb[15 + d*4 + k] = cosf(a);
            }
        }
        float rt = b0[j];
        #pragma unroll
        for (int i=0; i<27; i++)
            rt = fmaf(vemb[i], W0[(12+i)*WIDTH + j], rt);
        if (half == 0) rts[j] = rt;
    }

    const int m4 = lane & 3, ncol = lane >> 2;

    // ---- W1 B-fragments (fp16), warp owns N cols [16w,16w+16) ----
    uint Bq[8][2][2];
    float b1v[2][2];
    #pragma unroll
    for (int nt=0; nt<2; nt++){
        const int n = 16*warp + 8*nt + ncol;
        #pragma unroll
        for (int kt=0; kt<8; kt++){
            #pragma unroll
            for (int p=0; p<2; p++){
                int k = 16*kt + 2*m4 + 8*p;
                Bq[kt][nt][p] = packh2(W1[k*WIDTH + n], W1[(k+1)*WIDTH + n]);
            }
        }
        b1v[nt][0] = b1[16*warp + 8*nt + 2*m4];
        b1v[nt][1] = b1[16*warp + 8*nt + 2*m4 + 1];
    }

    // ---- W0 B-fragments (12 real rows, rows 12..15 zeroed) ----
    uint B0q[2][2];
    #pragma unroll
    for (int nt=0; nt<2; nt++){
        const int n = 16*warp + 8*nt + ncol;
        #pragma unroll
        for (int p=0; p<2; p++){
            int k = 2*m4 + 8*p;
            float wa = (k   < 12) ? W0[k*WIDTH + n]     : 0.f;
            float wb = (k+1 < 12) ? W0[(k+1)*WIDTH + n] : 0.f;
            B0q[nt][p] = packh2(wa, wb);
        }
    }

    __syncthreads();
    // rayterm accumulator-init values for this warp's columns
    float rt0[2], rt1[2];
    #pragma unroll
    for (int nt=0; nt<2; nt++){
        rt0[nt] = rts[16*warp + 8*nt + 2*m4];
        rt1[nt] = rts[16*warp + 8*nt + 2*m4 + 1];
    }

    // ldmatrix addresses
    const uint faddr  = (uint)__cvta_generic_to_shared(&fth[lane & 15][0]) + (uint)(lane >> 4)*16u;
    const uint haddr  = (uint)__cvta_generic_to_shared(&h0s[lane & 15][0]) + (uint)(lane >> 4)*16u;

    // sampling lane decomposition: lane = corner*4 + chunk
    const int q  = lane & 3;
    const int c8 = lane >> 2;
    const int cx = (c8 >> 2) & 1, cy = (c8 >> 1) & 1, cz = c8 & 1;

    float T = 1.f;
    float racc0=0.f, racc1=0.f, racc2=0.f;

    // ---- prefetch tile 0 gathers ----
    float4 pv[2]; float pw[2];
    #pragma unroll
    for (int rr=0; rr<2; rr++){
        const int s = warp + 8*rr;
        float t = 0.2f + (float)(s) * (1.6f/255.0f);
        float gx = fminf(fmaxf((fmaf(dx,t,ox)+1.f)*79.5f, 0.f), 159.f);
        float gy = fminf(fmaxf((fmaf(dy,t,oy)+1.f)*79.5f, 0.f), 159.f);
        float gz = fminf(fmaxf((fmaf(dz,t,oz)+1.f)*79.5f, 0.f), 159.f);
        int x0 = min((int)gx, 158), y0 = min((int)gy, 158), z0 = min((int)gz, 158);
        float ax = gx-(float)x0, ay = gy-(float)y0, az = gz-(float)z0;
        size_t vox = (size_t)((x0+cx)*GRID_N + (y0+cy))*GRID_N + (size_t)(z0+cz);
        pv[rr] = __ldg((const float4*)(g_vox + vox*16) + q);
        pw[rr] = (cx ? ax : 1.f-ax) * (cy ? ay : 1.f-ay) * (cz ? az : 1.f-az);
    }

    for (int tt=0; tt<NT; tt++){
        // ====== consume prefetched gathers: reduce + write fp16 A tile ========
        #pragma unroll
        for (int rr=0; rr<2; rr++){
            const int s = warp + 8*rr;
            float4 v = pv[rr];
            float wc = pw[rr];
            v.x *= wc; v.y *= wc; v.z *= wc; v.w *= wc;
            #pragma unroll
            for (int off=4; off<32; off<<=1){
                v.x += __shfl_xor_sync(0xffffffffu, v.x, off);
                v.y += __shfl_xor_sync(0xffffffffu, v.y, off);
                v.z += __shfl_xor_sync(0xffffffffu, v.z, off);
                v.w += __shfl_xor_sync(0xffffffffu, v.w, off);
            }
            if (lane < 4)
                *(uint2*)&fth[s][4*lane] = make_uint2(packh2(v.x, v.y), packh2(v.z, v.w));
            if (lane == 3) sigs[s] = v.x;    // channel 12 = sigma (exact fp32)
        }
        // ====== prefetch next tile (latency hides behind layer0+layer1) ======
        if (tt+1 < NT){
            #pragma unroll
            for (int rr=0; rr<2; rr++){
                const int s = warp + 8*rr;
                float t = 0.2f + (float)((tt+1)*SB + s) * (1.6f/255.0f);
                float gx = fminf(fmaxf((fmaf(dx,t,ox)+1.f)*79.5f, 0.f), 159.f);
                float gy = fminf(fmaxf((fmaf(dy,t,oy)+1.f)*79.5f, 0.f), 159.f);
                float gz = fminf(fmaxf((fmaf(dz,t,oz)+1.f)*79.5f, 0.f), 159.f);
                int x0 = min((int)gx, 158), y0 = min((int)gy, 158), z0 = min((int)gz, 158);
                float ax = gx-(float)x0, ay = gy-(float)y0, az = gz-(float)z0;
                size_t vox = (size_t)((x0+cx)*GRID_N + (y0+cy))*GRID_N + (size_t)(z0+cz);
                pv[rr] = __ldg((const float4*)(g_vox + vox*16) + q);
                pw[rr] = (cx ? ax : 1.f-ax) * (cy ? ay : 1.f-ay) * (cz ? az : 1.f-az);
            }
        }
        __syncthreads();

        // ============ transmittance (warp 0, sigma exact fp32) ===============
        if (warp == 0){
            if (lane < SB){
                float e = __expf(sigs[lane] + ACT_SHIFT);
                avs[lane] = 1.f - rsqrtf(1.f + e);
            }
            __syncwarp();
            if (lane == 0){
                #pragma unroll
                for (int s=0; s<SB; s++){
                    float a = avs[s];
                    wsm[s] = a * T;
                    T *= (1.f - a + 1e-10f);
                }
                if (tt == NT-1) alphainv_s = T;
            }
        }

        // ============ layer0: fp16 MMA, rayterm as C init ====================
        {
            float c[2][4];
            #pragma unroll
            for (int nt=0; nt<2; nt++){
                c[nt][0]=rt0[nt]; c[nt][1]=rt1[nt];
                c[nt][2]=rt0[nt]; c[nt][3]=rt1[nt];
            }
            uint a0,a1,a2,a3;
            LDSM_X4(a0,a1,a2,a3, faddr);
            #pragma unroll
            for (int nt=0; nt<2; nt++)
                MMA_F16(c[nt], a0,a1,a2,a3, B0q[nt][0], B0q[nt][1]);
            // epilogue: relu -> fp16 -> h0 tile (C layout == layer1 A rows)
            const int row = lane >> 2;
            #pragma unroll
            for (int nt=0; nt<2; nt++){
                const int n0 = 16*warp + 8*nt + 2*m4;
                *(uint*)&h0s[row][n0]   = packh2(fmaxf(c[nt][0],0.f), fmaxf(c[nt][1],0.f));
                *(uint*)&h0s[row+8][n0] = packh2(fmaxf(c[nt][2],0.f), fmaxf(c[nt][3],0.f));
            }
        }
        __syncthreads();

        // ============ layer1: fp16 MMA =======================================
        {
            float c0[2][4];
            #pragma unroll
            for (int nt=0; nt<2; nt++){
                c0[nt][0]=b1v[nt][0]; c0[nt][1]=b1v[nt][1];
                c0[nt][2]=b1v[nt][0]; c0[nt][3]=b1v[nt][1];
            }
            #pragma unroll
            for (int kt=0; kt<8; kt++){
                uint a0,a1,a2,a3;
                LDSM_X4(a0,a1,a2,a3, haddr + (uint)kt*32u);
                #pragma unroll
                for (int nt=0; nt<2; nt++)
                    MMA_F16(c0[nt], a0,a1,a2,a3, Bq[kt][nt][0], Bq[kt][nt][1]);
            }
            const int row = lane >> 2, cp = 2*(lane & 3);
            #pragma unroll
            for (int nt=0; nt<2; nt++){
                const int n0 = 16*warp + 8*nt + cp;
                *(float2*)&part[row][n0]   = make_float2(c0[nt][0], c0[nt][1]);
                *(float2*)&part[row+8][n0] = make_float2(c0[nt][2], c0[nt][3]);
            }
        }
        __syncthreads();

        // ============ layer2 + compositing: warp handles samples warp, warp+8 =
        #pragma unroll
        for (int rr=0; rr<2; rr++){
            const int s = warp + 8*rr;
            float p0=0.f, p1=0.f, p2=0.f;
            #pragma unroll
            for (int c=0; c<4; c++){
                int k = lane + 32*c;
                float h = fmaxf(part[s][k], 0.f);
                p0 = fmaf(h, W2s[3*k+0], p0);
                p1 = fmaf(h, W2s[3*k+1], p1);
                p2 = fmaf(h, W2s[3*k+2], p2);
            }
            #pragma unroll
            for (int off=16; off>0; off>>=1){
                p0 += __shfl_down_sync(0xffffffffu, p0, off);
                p1 += __shfl_down_sync(0xffffffffu, p1, off);
                p2 += __shfl_down_sync(0xffffffffu, p2, off);
            }
            if (lane == 0){
                float w = wsm[s];
                racc0 = fmaf(w, sigmoidf_(p0 + b2s[0]), racc0);
                racc1 = fmaf(w, sigmoidf_(p1 + b2s[1]), racc1);
                racc2 = fmaf(w, sigmoidf_(p2 + b2s[2]), racc2);
            }
        }
        // next tile's first __syncthreads orders all rewrites vs these reads
    }

    if (lane == 0){
        accw[warp][0] = racc0; accw[warp][1] = racc1; accw[warp][2] = racc2;
    }
    __syncthreads();
    if (tid < 3){
        float s = alphainv_s;
        #pragma unroll
        for (int w=0; w<8; w++) s += accw[w][tid];
        out[3*r + tid] = s;
    }
}

extern "C" void kernel_launch(void* const* d_in, const int* in_sizes, int n_in,
                              void* d_out, int out_size)
{
    const float* rays_o  = (const float*)d_in[0];
    const float* rays_d  = (const float*)d_in[1];
    const float* density = (const float*)d_in[2];
    const float* k0      = (const float*)d_in[3];
    const float* W0      = (const float*)d_in[4];
    const float* b0      = (const float*)d_in[5];
    const float* W1      = (const float*)d_in[6];
    const float* b1      = (const float*)d_in[7];
    const float* W2      = (const float*)d_in[8];
    const float* b2      = (const float*)d_in[9];
    float* out = (float*)d_out;

    repack_kernel<<<(G3 + 255)/256, 256>>>(density, k0);

    int n_rays = in_sizes[0] / 3;
    dvgo_fused<<<n_rays, 256>>>(rays_o, rays_d,
                                W0, b0, W1, b1, W2, b2, out);
}

// round 11
// speedup vs baseline: 3.9190x; 1.0190x over previous
#include <cuda_runtime.h>
#include <cuda_fp16.h>

#define GRID_N 160
#define G2 (GRID_N*GRID_N)
#define G3 (GRID_N*GRID_N*GRID_N)
#define NS 256
#define SB 16
#define NT (NS/SB)
#define WIDTH 128
#define ACT_SHIFT (-4.59511985013459f)   /* log(1/99) */

typedef unsigned int uint;

#define MMA_F16(C, A0,A1,A2,A3, B0,B1) \
    asm volatile("mma.sync.aligned.m16n8k16.row.col.f32.f16.f16.f32 " \
        "{%0,%1,%2,%3}, {%4,%5,%6,%7}, {%8,%9}, {%0,%1,%2,%3};" \
        : "+f"((C)[0]),"+f"((C)[1]),"+f"((C)[2]),"+f"((C)[3]) \
        : "r"(A0),"r"(A1),"r"(A2),"r"(A3), "r"(B0),"r"(B1))

#define LDSM_X4(R0,R1,R2,R3, ADDR) \
    asm volatile("ldmatrix.sync.aligned.m8n8.x4.shared.b16 {%0,%1,%2,%3}, [%4];" \
        : "=r"(R0),"=r"(R1),"=r"(R2),"=r"(R3) : "r"(ADDR))

__device__ __forceinline__ float sigmoidf_(float x){ return 1.f/(1.f+__expf(-x)); }

__device__ __forceinline__ uint packh2(float a, float b){
    __half2 h = __floats2half2_rn(a, b);
    return *(uint*)&h;
}

// Channels-last voxel store: [x][y][z][16] floats = 64B/voxel.
__device__ float g_vox[(size_t)G3 * 16];

__global__ __launch_bounds__(256)
void repack_kernel(const float* __restrict__ density, const float* __restrict__ k0)
{
    int v = blockIdx.x * 256 + threadIdx.x;
    if (v >= G3) return;
    float4 a, b, c, d;
    a.x = k0[0*G3+v];  a.y = k0[1*G3+v];  a.z = k0[2*G3+v];  a.w = k0[3*G3+v];
    b.x = k0[4*G3+v];  b.y = k0[5*G3+v];  b.z = k0[6*G3+v];  b.w = k0[7*G3+v];
    c.x = k0[8*G3+v];  c.y = k0[9*G3+v];  c.z = k0[10*G3+v]; c.w = k0[11*G3+v];
    d.x = density[v];  d.y = 0.f; d.z = 0.f; d.w = 0.f;
    float4* o = (float4*)(g_vox + (size_t)v * 16);
    o[0] = a; o[1] = b; o[2] = c; o[3] = d;
}

__global__ __launch_bounds__(256, 3)
void dvgo_fused(const float* __restrict__ rays_o, const float* __restrict__ rays_d,
                const float* __restrict__ W0, const float* __restrict__ b0,
                const float* __restrict__ W1, const float* __restrict__ b1,
                const float* __restrict__ W2, const float* __restrict__ b2,
                float* __restrict__ out)
{
    __shared__ __align__(16) __half fth[SB][16];     // feats fp16 (A tile, k=16)
    __shared__ __align__(16) __half h0s[SB][136];    // h0 fp16
    __shared__ __align__(16) float part[SB][132];    // layer1 out (pre-relu, b1 incl)
    __shared__ __align__(16) float W2s4[WIDTH][4];   // W2 padded: one LDS.128 per k
    __shared__ float sigs[SB], wsm[SB], avs[SB];
    __shared__ float rts[WIDTH];                     // rayterm per unit
    __shared__ float b2s[3];
    __shared__ float accw[8][3];
    __shared__ float alphainv_s;

    const int r    = blockIdx.x;
    const int tid  = threadIdx.x;
    const int lane = tid & 31;
    const int warp = tid >> 5;       // 0..7 : sample owner (sampling/layer2), N-slice (MMA)
    const int j    = tid & 127;
    const int half = tid >> 7;

    if (tid < WIDTH){
        W2s4[tid][0] = W2[3*tid+0];
        W2s4[tid][1] = W2[3*tid+1];
        W2s4[tid][2] = W2[3*tid+2];
        W2s4[tid][3] = 0.f;
    }
    if (tid < 3) b2s[tid] = b2[tid];

    const float ox = rays_o[3*r+0], oy = rays_o[3*r+1], oz = rays_o[3*r+2];
    const float dx = rays_d[3*r+0], dy = rays_d[3*r+1], dz = rays_d[3*r+2];

    // ---- per-ray constant: b0 + vemb@W0[12:39]  (exact fp32) ----
    {
        float inv = rsqrtf(dx*dx + dy*dy + dz*dz);
        float vd[3] = {dx*inv, dy*inv, dz*inv};
        float vemb[27];
        vemb[0]=vd[0]; vemb[1]=vd[1]; vemb[2]=vd[2];
        #pragma unroll
        for (int d=0; d<3; d++){
            #pragma unroll
            for (int k=0; k<4; k++){
                float a = vd[d] * (float)(1<<k);
                vemb[3  + d*4 + k] = sinf(a);
                vemb[15 + d*4 + k] = cosf(a);
            }
        }
        float rt = b0[j];
        #pragma unroll
        for (int i=0; i<27; i++)
            rt = fmaf(vemb[i], W0[(12+i)*WIDTH + j], rt);
        if (half == 0) rts[j] = rt;
    }

    const int m4 = lane & 3, ncol = lane >> 2;

    // ---- W1 B-fragments (fp16), warp owns N cols [16w,16w+16) ----
    uint Bq[8][2][2];
    float b1v[2][2];
    #pragma unroll
    for (int nt=0; nt<2; nt++){
        const int n = 16*warp + 8*nt + ncol;
        #pragma unroll
        for (int kt=0; kt<8; kt++){
            #pragma unroll
            for (int p=0; p<2; p++){
                int k = 16*kt + 2*m4 + 8*p;
                Bq[kt][nt][p] = packh2(W1[k*WIDTH + n], W1[(k+1)*WIDTH + n]);
            }
        }
        b1v[nt][0] = b1[16*warp + 8*nt + 2*m4];
        b1v[nt][1] = b1[16*warp + 8*nt + 2*m4 + 1];
    }

    // ---- W0 B-fragments (12 real rows, rows 12..15 zeroed) ----
    uint B0q[2][2];
    #pragma unroll
    for (int nt=0; nt<2; nt++){
        const int n = 16*warp + 8*nt + ncol;
        #pragma unroll
        for (int p=0; p<2; p++){
            int k = 2*m4 + 8*p;
            float wa = (k   < 12) ? W0[k*WIDTH + n]     : 0.f;
            float wb = (k+1 < 12) ? W0[(k+1)*WIDTH + n] : 0.f;
            B0q[nt][p] = packh2(wa, wb);
        }
    }

    __syncthreads();
    // rayterm accumulator-init values for this warp's columns
    float rt0[2], rt1[2];
    #pragma unroll
    for (int nt=0; nt<2; nt++){
        rt0[nt] = rts[16*warp + 8*nt + 2*m4];
        rt1[nt] = rts[16*warp + 8*nt + 2*m4 + 1];
    }

    // ldmatrix addresses
    const uint faddr  = (uint)__cvta_generic_to_shared(&fth[lane & 15][0]) + (uint)(lane >> 4)*16u;
    const uint haddr  = (uint)__cvta_generic_to_shared(&h0s[lane & 15][0]) + (uint)(lane >> 4)*16u;

    // sampling lane decomposition: lane = rr(1) | xy(2) | chunk(2)
    // thread owns sample (warp + 8*rr), xy-corner, channel-chunk q; loads both z corners.
    const int rr  = lane >> 4;          // sample half
    const int q   = lane & 3;           // float4 chunk
    const int xy  = (lane >> 2) & 3;
    const int cxk = xy & 1, cyk = xy >> 1;
    const int smp = warp + 8*rr;        // this thread's sample within tile
    const char* gvb = (const char*)g_vox;

    float T = 1.f;
    float racc0=0.f, racc1=0.f, racc2=0.f;

    // ---- prefetch tile 0 gathers (both z corners, 32-bit offsets) ----
    float4 pv0, pv1; float pwxy, paz;
    {
        float t = 0.2f + (float)(smp) * (1.6f/255.0f);
        float gx = fminf(fmaxf((fmaf(dx,t,ox)+1.f)*79.5f, 0.f), 159.f);
        float gy = fminf(fmaxf((fmaf(dy,t,oy)+1.f)*79.5f, 0.f), 159.f);
        float gz = fminf(fmaxf((fmaf(dz,t,oz)+1.f)*79.5f, 0.f), 159.f);
        int x0 = min((int)gx, 158), y0 = min((int)gy, 158), z0 = min((int)gz, 158);
        float ax = gx-(float)x0, ay = gy-(float)y0;
        paz = gz-(float)z0;
        uint off = (uint)(((x0+cxk)*GRID_N + (y0+cyk))*GRID_N + z0) * 64u + (uint)q*16u;
        pv0 = __ldg((const float4*)(gvb + off));
        pv1 = __ldg((const float4*)(gvb + off + 64u));
        pwxy = (cxk ? ax : 1.f-ax) * (cyk ? ay : 1.f-ay);
    }

    for (int tt=0; tt<NT; tt++){
        // ====== consume prefetched gathers: z-lerp, xy-reduce, fp16 A tile ====
        {
            float4 v;
            v.x = fmaf(paz, pv1.x - pv0.x, pv0.x) * pwxy;
            v.y = fmaf(paz, pv1.y - pv0.y, pv0.y) * pwxy;
            v.z = fmaf(paz, pv1.z - pv0.z, pv0.z) * pwxy;
            v.w = fmaf(paz, pv1.w - pv0.w, pv0.w) * pwxy;
            #pragma unroll
            for (int off=4; off<16; off<<=1){
                v.x += __shfl_xor_sync(0xffffffffu, v.x, off);
                v.y += __shfl_xor_sync(0xffffffffu, v.y, off);
                v.z += __shfl_xor_sync(0xffffffffu, v.z, off);
                v.w += __shfl_xor_sync(0xffffffffu, v.w, off);
            }
            if ((lane & 12) == 0)   // xy==0: canonical lanes, q = lane&3
                *(uint2*)&fth[smp][4*q] = make_uint2(packh2(v.x, v.y), packh2(v.z, v.w));
            if ((lane & 15) == 3) sigs[smp] = v.x;   // chunk 3 comp x = sigma (fp32)
        }
        // ====== prefetch next tile (latency hides behind layer0+layer1) ======
        if (tt+1 < NT){
            float t = 0.2f + (float)((tt+1)*SB + smp) * (1.6f/255.0f);
            float gx = fminf(fmaxf((fmaf(dx,t,ox)+1.f)*79.5f, 0.f), 159.f);
            float gy = fminf(fmaxf((fmaf(dy,t,oy)+1.f)*79.5f, 0.f), 159.f);
            float gz = fminf(fmaxf((fmaf(dz,t,oz)+1.f)*79.5f, 0.f), 159.f);
            int x0 = min((int)gx, 158), y0 = min((int)gy, 158), z0 = min((int)gz, 158);
            float ax = gx-(float)x0, ay = gy-(float)y0;
            paz = gz-(float)z0;
            uint off = (uint)(((x0+cxk)*GRID_N + (y0+cyk))*GRID_N + z0) * 64u + (uint)q*16u;
            pv0 = __ldg((const float4*)(gvb + off));
            pv1 = __ldg((const float4*)(gvb + off + 64u));
            pwxy = (cxk ? ax : 1.f-ax) * (cyk ? ay : 1.f-ay);
        }
        __syncthreads();

        // ============ transmittance (warp 0, sigma exact fp32) ===============
        if (warp == 0){
            if (lane < SB){
                float e = __expf(sigs[lane] + ACT_SHIFT);
                avs[lane] = 1.f - rsqrtf(1.f + e);
            }
            __syncwarp();
            if (lane == 0){
                #pragma unroll
                for (int s=0; s<SB; s++){
                    float a = avs[s];
                    wsm[s] = a * T;
                    T *= (1.f - a + 1e-10f);
                }
                if (tt == NT-1) alphainv_s = T;
            }
        }

        // ============ layer0: fp16 MMA, rayterm as C init ====================
        {
            float c[2][4];
            #pragma unroll
            for (int nt=0; nt<2; nt++){
                c[nt][0]=rt0[nt]; c[nt][1]=rt1[nt];
                c[nt][2]=rt0[nt]; c[nt][3]=rt1[nt];
            }
            uint a0,a1,a2,a3;
            LDSM_X4(a0,a1,a2,a3, faddr);
            #pragma unroll
            for (int nt=0; nt<2; nt++)
                MMA_F16(c[nt], a0,a1,a2,a3, B0q[nt][0], B0q[nt][1]);
            // epilogue: relu -> fp16 -> h0 tile (C layout == layer1 A rows)
            const int row = lane >> 2;
            #pragma unroll
            for (int nt=0; nt<2; nt++){
                const int n0 = 16*warp + 8*nt + 2*m4;
                *(uint*)&h0s[row][n0]   = packh2(fmaxf(c[nt][0],0.f), fmaxf(c[nt][1],0.f));
                *(uint*)&h0s[row+8][n0] = packh2(fmaxf(c[nt][2],0.f), fmaxf(c[nt][3],0.f));
            }
        }
        __syncthreads();

        // ============ layer1: fp16 MMA =======================================
        {
            float c0[2][4];
            #pragma unroll
            for (int nt=0; nt<2; nt++){
                c0[nt][0]=b1v[nt][0]; c0[nt][1]=b1v[nt][1];
                c0[nt][2]=b1v[nt][0]; c0[nt][3]=b1v[nt][1];
            }
            #pragma unroll
            for (int kt=0; kt<8; kt++){
                uint a0,a1,a2,a3;
                LDSM_X4(a0,a1,a2,a3, haddr + (uint)kt*32u);
                #pragma unroll
                for (int nt=0; nt<2; nt++)
                    MMA_F16(c0[nt], a0,a1,a2,a3, Bq[kt][nt][0], Bq[kt][nt][1]);
            }
            const int row = lane >> 2, cp = 2*(lane & 3);
            #pragma unroll
            for (int nt=0; nt<2; nt++){
                const int n0 = 16*warp + 8*nt + cp;
                *(float2*)&part[row][n0]   = make_float2(c0[nt][0], c0[nt][1]);
                *(float2*)&part[row+8][n0] = make_float2(c0[nt][2], c0[nt][3]);
            }
        }
        __syncthreads();

        // ============ layer2 + compositing: warp handles samples warp, warp+8 =
        #pragma unroll
        for (int rr2=0; rr2<2; rr2++){
            const int s = warp + 8*rr2;
            float p0=0.f, p1=0.f, p2=0.f;
            #pragma unroll
            for (int c=0; c<4; c++){
                int k = lane + 32*c;
                float h = fmaxf(part[s][k], 0.f);
                float4 wv = *(const float4*)&W2s4[k][0];
                p0 = fmaf(h, wv.x, p0);
                p1 = fmaf(h, wv.y, p1);
                p2 = fmaf(h, wv.z, p2);
            }
            #pragma unroll
            for (int off=16; off>0; off>>=1){
                p0 += __shfl_down_sync(0xffffffffu, p0, off);
                p1 += __shfl_down_sync(0xffffffffu, p1, off);
                p2 += __shfl_down_sync(0xffffffffu, p2, off);
            }
            if (lane == 0){
                float w = wsm[s];
                racc0 = fmaf(w, sigmoidf_(p0 + b2s[0]), racc0);
                racc1 = fmaf(w, sigmoidf_(p1 + b2s[1]), racc1);
                racc2 = fmaf(w, sigmoidf_(p2 + b2s[2]), racc2);
            }
        }
        // next tile's first __syncthreads orders all rewrites vs these reads
    }

    if (lane == 0){
        accw[warp][0] = racc0; accw[warp][1] = racc1; accw[warp][2] = racc2;
    }
    __syncthreads();
    if (tid < 3){
        float s = alphainv_s;
        #pragma unroll
        for (int w=0; w<8; w++) s += accw[w][tid];
        out[3*r + tid] = s;
    }
}

extern "C" void kernel_launch(void* const* d_in, const int* in_sizes, int n_in,
                              void* d_out, int out_size)
{
    const float* rays_o  = (const float*)d_in[0];
    const float* rays_d  = (const float*)d_in[1];
    const float* density = (const float*)d_in[2];
    const float* k0      = (const float*)d_in[3];
    const float* W0      = (const float*)d_in[4];
    const float* b0      = (const float*)d_in[5];
    const float* W1      = (const float*)d_in[6];
    const float* b1      = (const float*)d_in[7];
    const float* W2      = (const float*)d_in[8];
    const float* b2      = (const float*)d_in[9];
    float* out = (float*)d_out;

    repack_kernel<<<(G3 + 255)/256, 256>>>(density, k0);

    int n_rays = in_sizes[0] / 3;
    dvgo_fused<<<n_rays, 256>>>(rays_o, rays_d,
                                W0, b0, W1, b1, W2, b2, out);
}

// round 12
// speedup vs baseline: 4.2914x; 1.0950x over previous
#include <cuda_runtime.h>
#include <cuda_fp16.h>

#define GRID_N 160
#define G2 (GRID_N*GRID_N)
#define G3 (GRID_N*GRID_N*GRID_N)
#define NS 256
#define SB 16
#define NT (NS/SB)
#define WIDTH 128
#define ACT_SHIFT (-4.59511985013459f)   /* log(1/99) */

typedef unsigned int uint;

#define MMA_F16(C, A0,A1,A2,A3, B0,B1) \
    asm volatile("mma.sync.aligned.m16n8k16.row.col.f32.f16.f16.f32 " \
        "{%0,%1,%2,%3}, {%4,%5,%6,%7}, {%8,%9}, {%0,%1,%2,%3};" \
        : "+f"((C)[0]),"+f"((C)[1]),"+f"((C)[2]),"+f"((C)[3]) \
        : "r"(A0),"r"(A1),"r"(A2),"r"(A3), "r"(B0),"r"(B1))

#define LDSM_X4(R0,R1,R2,R3, ADDR) \
    asm volatile("ldmatrix.sync.aligned.m8n8.x4.shared.b16 {%0,%1,%2,%3}, [%4];" \
        : "=r"(R0),"=r"(R1),"=r"(R2),"=r"(R3) : "r"(ADDR))

__device__ __forceinline__ float sigmoidf_(float x){ return 1.f/(1.f+__expf(-x)); }

__device__ __forceinline__ uint packh2(float a, float b){
    __half2 h = __floats2half2_rn(a, b);
    return *(uint*)&h;
}

// Channels-last voxel store: [x][y][z][16] floats = 64B/voxel.
__device__ float g_vox[(size_t)G3 * 16];

__global__ __launch_bounds__(256)
void repack_kernel(const float* __restrict__ density, const float* __restrict__ k0)
{
    int v = blockIdx.x * 256 + threadIdx.x;
    if (v >= G3) return;
    float4 a, b, c, d;
    a.x = k0[0*G3+v];  a.y = k0[1*G3+v];  a.z = k0[2*G3+v];  a.w = k0[3*G3+v];
    b.x = k0[4*G3+v];  b.y = k0[5*G3+v];  b.z = k0[6*G3+v];  b.w = k0[7*G3+v];
    c.x = k0[8*G3+v];  c.y = k0[9*G3+v];  c.z = k0[10*G3+v]; c.w = k0[11*G3+v];
    d.x = density[v];  d.y = 0.f; d.z = 0.f; d.w = 0.f;
    float4* o = (float4*)(g_vox + (size_t)v * 16);
    o[0] = a; o[1] = b; o[2] = c; o[3] = d;
}

__global__ __launch_bounds__(256, 3)
void dvgo_fused(const float* __restrict__ rays_o, const float* __restrict__ rays_d,
                const float* __restrict__ W0, const float* __restrict__ b0,
                const float* __restrict__ W1, const float* __restrict__ b1,
                const float* __restrict__ W2, const float* __restrict__ b2,
                float* __restrict__ out)
{
    __shared__ __align__(16) __half fth[SB][16];     // feats fp16 (A tile, k=16)
    __shared__ __align__(16) __half h0s[SB][136];    // h0 fp16
    __shared__ __align__(16) float part2[8][SB][4];  // per-warp layer2 K-slice partials
    __shared__ float sigs[SB], wsm[SB], avs[SB];
    __shared__ float rts[WIDTH];                     // rayterm per unit
    __shared__ float b2s[3];
    __shared__ float accw[8][3];
    __shared__ float alphainv_s;

    const int r    = blockIdx.x;
    const int tid  = threadIdx.x;
    const int lane = tid & 31;
    const int warp = tid >> 5;       // 0..7 : sample owner, N-slice (MMA), K-slice (layer2)
    const int j    = tid & 127;
    const int half = tid >> 7;

    if (tid < 3) b2s[tid] = b2[tid];

    const float ox = rays_o[3*r+0], oy = rays_o[3*r+1], oz = rays_o[3*r+2];
    const float dx = rays_d[3*r+0], dy = rays_d[3*r+1], dz = rays_d[3*r+2];

    // ---- per-ray constant: b0 + vemb@W0[12:39]  (exact fp32) ----
    {
        float inv = rsqrtf(dx*dx + dy*dy + dz*dz);
        float vd[3] = {dx*inv, dy*inv, dz*inv};
        float vemb[27];
        vemb[0]=vd[0]; vemb[1]=vd[1]; vemb[2]=vd[2];
        #pragma unroll
        for (int d=0; d<3; d++){
            #pragma unroll
            for (int k=0; k<4; k++){
                float a = vd[d] * (float)(1<<k);
                vemb[3  + d*4 + k] = sinf(a);
                vemb[15 + d*4 + k] = cosf(a);
            }
        }
        float rt = b0[j];
        #pragma unroll
        for (int i=0; i<27; i++)
            rt = fmaf(vemb[i], W0[(12+i)*WIDTH + j], rt);
        if (half == 0) rts[j] = rt;
    }

    const int m4 = lane & 3, ncol = lane >> 2;

    // ---- W1 B-fragments (fp16), warp owns N cols [16w,16w+16) ----
    uint Bq[8][2][2];
    float b1v[2][2];
    #pragma unroll
    for (int nt=0; nt<2; nt++){
        const int n = 16*warp + 8*nt + ncol;
        #pragma unroll
        for (int kt=0; kt<8; kt++){
            #pragma unroll
            for (int p=0; p<2; p++){
                int k = 16*kt + 2*m4 + 8*p;
                Bq[kt][nt][p] = packh2(W1[k*WIDTH + n], W1[(k+1)*WIDTH + n]);
            }
        }
        b1v[nt][0] = b1[16*warp + 8*nt + 2*m4];
        b1v[nt][1] = b1[16*warp + 8*nt + 2*m4 + 1];
    }

    // ---- W0 B-fragments (12 real rows, rows 12..15 zeroed) ----
    uint B0q[2][2];
    #pragma unroll
    for (int nt=0; nt<2; nt++){
        const int n = 16*warp + 8*nt + ncol;
        #pragma unroll
        for (int p=0; p<2; p++){
            int k = 2*m4 + 8*p;
            float wa = (k   < 12) ? W0[k*WIDTH + n]     : 0.f;
            float wb = (k+1 < 12) ? W0[(k+1)*WIDTH + n] : 0.f;
            B0q[nt][p] = packh2(wa, wb);
        }
    }

    // ---- W2 B-fragment: K-slice rows [16w,16w+16), N=8 (cols 0..2 real) ----
    uint B2q[2];
    #pragma unroll
    for (int p=0; p<2; p++){
        int k = 16*warp + 2*m4 + 8*p;
        float wa = (ncol < 3) ? W2[k*3 + ncol]     : 0.f;
        float wb = (ncol < 3) ? W2[(k+1)*3 + ncol] : 0.f;
        B2q[p] = packh2(wa, wb);
    }

    __syncthreads();
    // rayterm accumulator-init values for this warp's columns
    float rt0[2], rt1[2];
    #pragma unroll
    for (int nt=0; nt<2; nt++){
        rt0[nt] = rts[16*warp + 8*nt + 2*m4];
        rt1[nt] = rts[16*warp + 8*nt + 2*m4 + 1];
    }

    // ldmatrix addresses
    const uint faddr  = (uint)__cvta_generic_to_shared(&fth[lane & 15][0]) + (uint)(lane >> 4)*16u;
    const uint haddr  = (uint)__cvta_generic_to_shared(&h0s[lane & 15][0]) + (uint)(lane >> 4)*16u;

    // sampling lane decomposition: lane = rr(1) | xy(2) | chunk(2)
    const int rr  = lane >> 4;          // sample half
    const int q   = lane & 3;           // float4 chunk
    const int xy  = (lane >> 2) & 3;
    const int cxk = xy & 1, cyk = xy >> 1;
    const int smp = warp + 8*rr;        // this thread's sample within tile
    const char* gvb = (const char*)g_vox;

    float T = 1.f;
    float racc0=0.f, racc1=0.f, racc2=0.f;

    // ---- prefetch tile 0 gathers (both z corners, 32-bit offsets) ----
    float4 pv0, pv1; float pwxy, paz;
    {
        float t = 0.2f + (float)(smp) * (1.6f/255.0f);
        float gx = fminf(fmaxf((fmaf(dx,t,ox)+1.f)*79.5f, 0.f), 159.f);
        float gy = fminf(fmaxf((fmaf(dy,t,oy)+1.f)*79.5f, 0.f), 159.f);
        float gz = fminf(fmaxf((fmaf(dz,t,oz)+1.f)*79.5f, 0.f), 159.f);
        int x0 = min((int)gx, 158), y0 = min((int)gy, 158), z0 = min((int)gz, 158);
        float ax = gx-(float)x0, ay = gy-(float)y0;
        paz = gz-(float)z0;
        uint off = (uint)(((x0+cxk)*GRID_N + (y0+cyk))*GRID_N + z0) * 64u + (uint)q*16u;
        pv0 = __ldg((const float4*)(gvb + off));
        pv1 = __ldg((const float4*)(gvb + off + 64u));
        pwxy = (cxk ? ax : 1.f-ax) * (cyk ? ay : 1.f-ay);
    }

    for (int tt=0; tt<NT; tt++){
        // ====== consume prefetched gathers: z-lerp, xy-reduce, fp16 A tile ====
        {
            float4 v;
            v.x = fmaf(paz, pv1.x - pv0.x, pv0.x) * pwxy;
            v.y = fmaf(paz, pv1.y - pv0.y, pv0.y) * pwxy;
            v.z = fmaf(paz, pv1.z - pv0.z, pv0.z) * pwxy;
            v.w = fmaf(paz, pv1.w - pv0.w, pv0.w) * pwxy;
            #pragma unroll
            for (int off=4; off<16; off<<=1){
                v.x += __shfl_xor_sync(0xffffffffu, v.x, off);
                v.y += __shfl_xor_sync(0xffffffffu, v.y, off);
                v.z += __shfl_xor_sync(0xffffffffu, v.z, off);
                v.w += __shfl_xor_sync(0xffffffffu, v.w, off);
            }
            if ((lane & 12) == 0)   // xy==0: canonical lanes, q = lane&3
                *(uint2*)&fth[smp][4*q] = make_uint2(packh2(v.x, v.y), packh2(v.z, v.w));
            if ((lane & 15) == 3) sigs[smp] = v.x;   // chunk 3 comp x = sigma (fp32)
        }
        // ====== prefetch next tile (latency hides behind layer0+layer1) ======
        if (tt+1 < NT){
            float t = 0.2f + (float)((tt+1)*SB + smp) * (1.6f/255.0f);
            float gx = fminf(fmaxf((fmaf(dx,t,ox)+1.f)*79.5f, 0.f), 159.f);
            float gy = fminf(fmaxf((fmaf(dy,t,oy)+1.f)*79.5f, 0.f), 159.f);
            float gz = fminf(fmaxf((fmaf(dz,t,oz)+1.f)*79.5f, 0.f), 159.f);
            int x0 = min((int)gx, 158), y0 = min((int)gy, 158), z0 = min((int)gz, 158);
            float ax = gx-(float)x0, ay = gy-(float)y0;
            paz = gz-(float)z0;
            uint off = (uint)(((x0+cxk)*GRID_N + (y0+cyk))*GRID_N + z0) * 64u + (uint)q*16u;
            pv0 = __ldg((const float4*)(gvb + off));
            pv1 = __ldg((const float4*)(gvb + off + 64u));
            pwxy = (cxk ? ax : 1.f-ax) * (cyk ? ay : 1.f-ay);
        }
        __syncthreads();   // B1: fth/sigs visible

        // ============ transmittance (warp 0, sigma exact fp32) ===============
        if (warp == 0){
            if (lane < SB){
                float e = __expf(sigs[lane] + ACT_SHIFT);
                avs[lane] = 1.f - rsqrtf(1.f + e);
            }
            __syncwarp();
            if (lane == 0){
                #pragma unroll
                for (int s=0; s<SB; s++){
                    float a = avs[s];
                    wsm[s] = a * T;
                    T *= (1.f - a + 1e-10f);
                }
                if (tt == NT-1) alphainv_s = T;
            }
        }

        // ============ layer0: fp16 MMA, rayterm as C init ====================
        {
            float c[2][4];
            #pragma unroll
            for (int nt=0; nt<2; nt++){
                c[nt][0]=rt0[nt]; c[nt][1]=rt1[nt];
                c[nt][2]=rt0[nt]; c[nt][3]=rt1[nt];
            }
            uint a0,a1,a2,a3;
            LDSM_X4(a0,a1,a2,a3, faddr);
            #pragma unroll
            for (int nt=0; nt<2; nt++)
                MMA_F16(c[nt], a0,a1,a2,a3, B0q[nt][0], B0q[nt][1]);
            // epilogue: relu -> fp16 -> h0 tile (C layout == layer1 A rows)
            const int row = lane >> 2;
            #pragma unroll
            for (int nt=0; nt<2; nt++){
                const int n0 = 16*warp + 8*nt + 2*m4;
                *(uint*)&h0s[row][n0]   = packh2(fmaxf(c[nt][0],0.f), fmaxf(c[nt][1],0.f));
                *(uint*)&h0s[row+8][n0] = packh2(fmaxf(c[nt][2],0.f), fmaxf(c[nt][3],0.f));
            }
        }
        __syncthreads();   // B2: h0s visible

        // ============ layer1 MMA + layer2 MMA fused in registers =============
        {
            float c0[2][4];
            #pragma unroll
            for (int nt=0; nt<2; nt++){
                c0[nt][0]=b1v[nt][0]; c0[nt][1]=b1v[nt][1];
                c0[nt][2]=b1v[nt][0]; c0[nt][3]=b1v[nt][1];
            }
            #pragma unroll
            for (int kt=0; kt<8; kt++){
                uint a0,a1,a2,a3;
                LDSM_X4(a0,a1,a2,a3, haddr + (uint)kt*32u);
                #pragma unroll
                for (int nt=0; nt<2; nt++)
                    MMA_F16(c0[nt], a0,a1,a2,a3, Bq[kt][nt][0], Bq[kt][nt][1]);
            }
            // relu + pack layer1 C directly into layer2 A-fragment (reg-layout identity):
            // a0 = A[g][2t,2t+1] = c0[0][0..1], a1 = A[g+8][2t,2t+1] = c0[0][2..3],
            // a2 = A[g][2t+8,..] = c0[1][0..1], a3 = A[g+8][2t+8,..] = c0[1][2..3]
            uint a0 = packh2(fmaxf(c0[0][0],0.f), fmaxf(c0[0][1],0.f));
            uint a1 = packh2(fmaxf(c0[0][2],0.f), fmaxf(c0[0][3],0.f));
            uint a2 = packh2(fmaxf(c0[1][0],0.f), fmaxf(c0[1][1],0.f));
            uint a3 = packh2(fmaxf(c0[1][2],0.f), fmaxf(c0[1][3],0.f));
            float cc[4] = {0.f, 0.f, 0.f, 0.f};
            MMA_F16(cc, a0,a1,a2,a3, B2q[0], B2q[1]);
            // cc = partial rgb for K-slice [16w,16w+16): rows {g,g+8}, cols {2t,2t+1}
            const int row = lane >> 2;
            if (m4 < 2){
                *(float2*)&part2[warp][row][2*m4]   = make_float2(cc[0], cc[1]);
                *(float2*)&part2[warp][row+8][2*m4] = make_float2(cc[2], cc[3]);
            }
        }
        __syncthreads();   // B3: part2/wsm visible

        // ============ cross-warp partial sum + compositing ===================
        #pragma unroll
        for (int rr2=0; rr2<2; rr2++){
            const int s = warp + 8*rr2;
            float4 p = *(const float4*)&part2[0][s][0];
            #pragma unroll
            for (int w2=1; w2<8; w2++){
                float4 v = *(const float4*)&part2[w2][s][0];
                p.x += v.x; p.y += v.y; p.z += v.z;
            }
            if (lane == 0){
                float w = wsm[s];
                racc0 = fmaf(w, sigmoidf_(p.x + b2s[0]), racc0);
                racc1 = fmaf(w, sigmoidf_(p.y + b2s[1]), racc1);
                racc2 = fmaf(w, sigmoidf_(p.z + b2s[2]), racc2);
            }
        }
        // next tile's B1 orders all rewrites vs these reads
    }

    if (lane == 0){
        accw[warp][0] = racc0; accw[warp][1] = racc1; accw[warp][2] = racc2;
    }
    __syncthreads();
    if (tid < 3){
        float s = alphainv_s;
        #pragma unroll
        for (int w=0; w<8; w++) s += accw[w][tid];
        out[3*r + tid] = s;
    }
}

extern "C" void kernel_launch(void* const* d_in, const int* in_sizes, int n_in,
                              void* d_out, int out_size)
{
    const float* rays_o  = (const float*)d_in[0];
    const float* rays_d  = (const float*)d_in[1];
    const float* density = (const float*)d_in[2];
    const float* k0      = (const float*)d_in[3];
    const float* W0      = (const float*)d_in[4];
    const float* b0      = (const float*)d_in[5];
    const float* W1      = (const float*)d_in[6];
    const float* b1      = (const float*)d_in[7];
    const float* W2      = (const float*)d_in[8];
    const float* b2      = (const float*)d_in[9];
    float* out = (float*)d_out;

    repack_kernel<<<(G3 + 255)/256, 256>>>(density, k0);

    int n_rays = in_sizes[0] / 3;
    dvgo_fused<<<n_rays, 256>>>(rays_o, rays_d,
                                W0, b0, W1, b1, W2, b2, out);
}

// round 13
// speedup vs baseline: 5.2629x; 1.2264x over previous
#include <cuda_runtime.h>
#include <cuda_fp16.h>

#define GRID_N 160
#define G2 (GRID_N*GRID_N)
#define G3 (GRID_N*GRID_N*GRID_N)
#define NS 256
#define SB 16
#define NT (NS/SB)
#define WIDTH 128
#define ACT_SHIFT (-4.59511985013459f)   /* log(1/99) */

typedef unsigned int uint;

#define MMA_F16(C, A0,A1,A2,A3, B0,B1) \
    asm volatile("mma.sync.aligned.m16n8k16.row.col.f32.f16.f16.f32 " \
        "{%0,%1,%2,%3}, {%4,%5,%6,%7}, {%8,%9}, {%0,%1,%2,%3};" \
        : "+f"((C)[0]),"+f"((C)[1]),"+f"((C)[2]),"+f"((C)[3]) \
        : "r"(A0),"r"(A1),"r"(A2),"r"(A3), "r"(B0),"r"(B1))

#define LDSM_X4(R0,R1,R2,R3, ADDR) \
    asm volatile("ldmatrix.sync.aligned.m8n8.x4.shared.b16 {%0,%1,%2,%3}, [%4];" \
        : "=r"(R0),"=r"(R1),"=r"(R2),"=r"(R3) : "r"(ADDR))

__device__ __forceinline__ float sigmoidf_(float x){ return 1.f/(1.f+__expf(-x)); }

__device__ __forceinline__ uint packh2(float a, float b){
    __half2 h = __floats2half2_rn(a, b);
    return *(uint*)&h;
}

// fp16 voxel store: 32B/voxel = 12 half channels (24B) + fp32 sigma (4B) + pad.
__device__ uint4 g_vox[(size_t)G3 * 2];

__global__ __launch_bounds__(256)
void repack_kernel(const float* __restrict__ density, const float* __restrict__ k0)
{
    int v = blockIdx.x * 256 + threadIdx.x;
    if (v >= G3) return;
    uint4 A, B;
    A.x = packh2(k0[0*G3+v],  k0[1*G3+v]);
    A.y = packh2(k0[2*G3+v],  k0[3*G3+v]);
    A.z = packh2(k0[4*G3+v],  k0[5*G3+v]);
    A.w = packh2(k0[6*G3+v],  k0[7*G3+v]);
    B.x = packh2(k0[8*G3+v],  k0[9*G3+v]);
    B.y = packh2(k0[10*G3+v], k0[11*G3+v]);
    B.z = __float_as_uint(density[v]);
    B.w = 0u;
    g_vox[2*(size_t)v]   = A;
    g_vox[2*(size_t)v+1] = B;
}

// unpack gathered uint2: q<3 -> 4 fp16 channels; q==3 -> fp32 sigma in .x, rest 0
__device__ __forceinline__ float4 unp_(uint2 u, int q){
    if (q < 3){
        float2 a = __half22float2(*(__half2*)&u.x);
        float2 b = __half22float2(*(__half2*)&u.y);
        return make_float4(a.x, a.y, b.x, b.y);
    }
    return make_float4(__uint_as_float(u.x), 0.f, 0.f, 0.f);
}

__global__ __launch_bounds__(256, 3)
void dvgo_fused(const float* __restrict__ rays_o, const float* __restrict__ rays_d,
                const float* __restrict__ W0, const float* __restrict__ b0,
                const float* __restrict__ W1, const float* __restrict__ b1,
                const float* __restrict__ W2, const float* __restrict__ b2,
                float* __restrict__ out)
{
    __shared__ __align__(16) __half fth[SB][16];     // feats fp16 (A tile, k=16)
    __shared__ __align__(16) __half h0s[SB][136];    // h0 fp16
    __shared__ __align__(16) float part2[SB][8][4];  // [s][swizzled w][rgb+pad]
    __shared__ float sigs[SB], wsm[SB];
    __shared__ float rts[WIDTH];                     // rayterm per unit
    __shared__ float b2s[3];
    __shared__ float accw[8][3];
    __shared__ float alphainv_s;

    const int r    = blockIdx.x;
    const int tid  = threadIdx.x;
    const int lane = tid & 31;
    const int warp = tid >> 5;       // 0..7 : sample owner, N-slice (MMA), K-slice (layer2)
    const int j    = tid & 127;
    const int half = tid >> 7;

    if (tid < 3) b2s[tid] = b2[tid];

    const float ox = rays_o[3*r+0], oy = rays_o[3*r+1], oz = rays_o[3*r+2];
    const float dx = rays_d[3*r+0], dy = rays_d[3*r+1], dz = rays_d[3*r+2];

    // ---- per-ray constant: b0 + vemb@W0[12:39]  (exact fp32) ----
    {
        float inv = rsqrtf(dx*dx + dy*dy + dz*dz);
        float vd[3] = {dx*inv, dy*inv, dz*inv};
        float vemb[27];
        vemb[0]=vd[0]; vemb[1]=vd[1]; vemb[2]=vd[2];
        #pragma unroll
        for (int d=0; d<3; d++){
            #pragma unroll
            for (int k=0; k<4; k++){
                float a = vd[d] * (float)(1<<k);
                vemb[3  + d*4 + k] = sinf(a);
                vemb[15 + d*4 + k] = cosf(a);
            }
        }
        float rt = b0[j];
        #pragma unroll
        for (int i=0; i<27; i++)
            rt = fmaf(vemb[i], W0[(12+i)*WIDTH + j], rt);
        if (half == 0) rts[j] = rt;
    }

    const int m4 = lane & 3, ncol = lane >> 2;

    // ---- W1 B-fragments (fp16), warp owns N cols [16w,16w+16) ----
    uint Bq[8][2][2];
    float b1v[2][2];
    #pragma unroll
    for (int nt=0; nt<2; nt++){
        const int n = 16*warp + 8*nt + ncol;
        #pragma unroll
        for (int kt=0; kt<8; kt++){
            #pragma unroll
            for (int p=0; p<2; p++){
                int k = 16*kt + 2*m4 + 8*p;
                Bq[kt][nt][p] = packh2(W1[k*WIDTH + n], W1[(k+1)*WIDTH + n]);
            }
        }
        b1v[nt][0] = b1[16*warp + 8*nt + 2*m4];
        b1v[nt][1] = b1[16*warp + 8*nt + 2*m4 + 1];
    }

    // ---- W0 B-fragments (12 real rows, rows 12..15 zeroed) ----
    uint B0q[2][2];
    #pragma unroll
    for (int nt=0; nt<2; nt++){
        const int n = 16*warp + 8*nt + ncol;
        #pragma unroll
        for (int p=0; p<2; p++){
            int k = 2*m4 + 8*p;
            float wa = (k   < 12) ? W0[k*WIDTH + n]     : 0.f;
            float wb = (k+1 < 12) ? W0[(k+1)*WIDTH + n] : 0.f;
            B0q[nt][p] = packh2(wa, wb);
        }
    }

    // ---- W2 B-fragment: K-slice rows [16w,16w+16), N=8 (cols 0..2 real) ----
    uint B2q[2];
    #pragma unroll
    for (int p=0; p<2; p++){
        int k = 16*warp + 2*m4 + 8*p;
        float wa = (ncol < 3) ? W2[k*3 + ncol]     : 0.f;
        float wb = (ncol < 3) ? W2[(k+1)*3 + ncol] : 0.f;
        B2q[p] = packh2(wa, wb);
    }

    __syncthreads();
    // rayterm accumulator-init values for this warp's columns
    float rt0[2], rt1[2];
    #pragma unroll
    for (int nt=0; nt<2; nt++){
        rt0[nt] = rts[16*warp + 8*nt + 2*m4];
        rt1[nt] = rts[16*warp + 8*nt + 2*m4 + 1];
    }

    // ldmatrix addresses
    const uint faddr  = (uint)__cvta_generic_to_shared(&fth[lane & 15][0]) + (uint)(lane >> 4)*16u;
    const uint haddr  = (uint)__cvta_generic_to_shared(&h0s[lane & 15][0]) + (uint)(lane >> 4)*16u;

    // sampling lane decomposition: lane = rr(1) | xy(2) | chunk(2)
    const int rr  = lane >> 4;          // sample half
    const int q   = lane & 3;           // channel chunk (3 = sigma)
    const int xy  = (lane >> 2) & 3;
    const int cxk = xy & 1, cyk = xy >> 1;
    const int smp = warp + 8*rr;        // this thread's sample within tile
    const char* gvb = (const char*)g_vox;

    float T = 1.f;
    float racc0=0.f, racc1=0.f, racc2=0.f;

    // ---- prefetch tile 0 gathers (both z corners, raw fp16 payload) ----
    uint2 pu0, pu1; float pwxy, paz;
    {
        float t = 0.2f + (float)(smp) * (1.6f/255.0f);
        float gx = fminf(fmaxf((fmaf(dx,t,ox)+1.f)*79.5f, 0.f), 159.f);
        float gy = fminf(fmaxf((fmaf(dy,t,oy)+1.f)*79.5f, 0.f), 159.f);
        float gz = fminf(fmaxf((fmaf(dz,t,oz)+1.f)*79.5f, 0.f), 159.f);
        int x0 = min((int)gx, 158), y0 = min((int)gy, 158), z0 = min((int)gz, 158);
        float ax = gx-(float)x0, ay = gy-(float)y0;
        paz = gz-(float)z0;
        uint off = (uint)(((x0+cxk)*GRID_N + (y0+cyk))*GRID_N + z0) * 32u + (uint)q*8u;
        pu0 = __ldg((const uint2*)(gvb + off));
        pu1 = __ldg((const uint2*)(gvb + off + 32u));
        pwxy = (cxk ? ax : 1.f-ax) * (cyk ? ay : 1.f-ay);
    }

    for (int tt=0; tt<NT; tt++){
        // ====== consume prefetched gathers: unpack, z-lerp, xy-reduce =========
        {
            float4 v0 = unp_(pu0, q), v1 = unp_(pu1, q);
            float4 v;
            v.x = fmaf(paz, v1.x - v0.x, v0.x) * pwxy;
            v.y = fmaf(paz, v1.y - v0.y, v0.y) * pwxy;
            v.z = fmaf(paz, v1.z - v0.z, v0.z) * pwxy;
            v.w = fmaf(paz, v1.w - v0.w, v0.w) * pwxy;
            #pragma unroll
            for (int off=4; off<16; off<<=1){
                v.x += __shfl_xor_sync(0xffffffffu, v.x, off);
                v.y += __shfl_xor_sync(0xffffffffu, v.y, off);
                v.z += __shfl_xor_sync(0xffffffffu, v.z, off);
                v.w += __shfl_xor_sync(0xffffffffu, v.w, off);
            }
            if ((lane & 12) == 0)   // xy==0 lanes; q==3 naturally writes (sig,0,0,0)
                *(uint2*)&fth[smp][4*q] = make_uint2(packh2(v.x, v.y), packh2(v.z, v.w));
            if ((lane & 15) == 3) sigs[smp] = v.x;   // sigma (exact fp32)
        }
        // ====== prefetch next tile (latency hides behind layer0+layer1) ======
        if (tt+1 < NT){
            float t = 0.2f + (float)((tt+1)*SB + smp) * (1.6f/255.0f);
            float gx = fminf(fmaxf((fmaf(dx,t,ox)+1.f)*79.5f, 0.f), 159.f);
            float gy = fminf(fmaxf((fmaf(dy,t,oy)+1.f)*79.5f, 0.f), 159.f);
            float gz = fminf(fmaxf((fmaf(dz,t,oz)+1.f)*79.5f, 0.f), 159.f);
            int x0 = min((int)gx, 158), y0 = min((int)gy, 158), z0 = min((int)gz, 158);
            float ax = gx-(float)x0, ay = gy-(float)y0;
            paz = gz-(float)z0;
            uint off = (uint)(((x0+cxk)*GRID_N + (y0+cyk))*GRID_N + z0) * 32u + (uint)q*8u;
            pu0 = __ldg((const uint2*)(gvb + off));
            pu1 = __ldg((const uint2*)(gvb + off + 32u));
            pwxy = (cxk ? ax : 1.f-ax) * (cyk ? ay : 1.f-ay);
        }
        __syncthreads();   // B1: fth/sigs visible

        // ============ transmittance (warp 0): parallel log/exp scan ===========
        if (warp == 0){
            float a = 0.f, lg = 0.f;
            if (lane < SB){
                float e = __expf(sigs[lane] + ACT_SHIFT);
                a  = 1.f - rsqrtf(1.f + e);
                lg = __logf(1.f - a + 1e-10f);
            }
            float sc = lg;
            #pragma unroll
            for (int d=1; d<16; d<<=1){
                float n = __shfl_up_sync(0xffffffffu, sc, d);
                if (lane >= d) sc += n;
            }
            if (lane < SB)
                wsm[lane] = a * T * __expf(sc - lg);     // exclusive prefix
            float tot = __shfl_sync(0xffffffffu, sc, 15);
            T *= __expf(tot);
            if (tt == NT-1 && lane == 0) alphainv_s = T;
        }

        // ============ layer0: fp16 MMA, rayterm as C init ====================
        {
            float c[2][4];
            #pragma unroll
            for (int nt=0; nt<2; nt++){
                c[nt][0]=rt0[nt]; c[nt][1]=rt1[nt];
                c[nt][2]=rt0[nt]; c[nt][3]=rt1[nt];
            }
            uint a0,a1,a2,a3;
            LDSM_X4(a0,a1,a2,a3, faddr);
            #pragma unroll
            for (int nt=0; nt<2; nt++)
                MMA_F16(c[nt], a0,a1,a2,a3, B0q[nt][0], B0q[nt][1]);
            // epilogue: relu -> fp16 -> h0 tile (C layout == layer1 A rows)
            const int row = lane >> 2;
            #pragma unroll
            for (int nt=0; nt<2; nt++){
                const int n0 = 16*warp + 8*nt + 2*m4;
                *(uint*)&h0s[row][n0]   = packh2(fmaxf(c[nt][0],0.f), fmaxf(c[nt][1],0.f));
                *(uint*)&h0s[row+8][n0] = packh2(fmaxf(c[nt][2],0.f), fmaxf(c[nt][3],0.f));
            }
        }
        __syncthreads();   // B2: h0s visible

        // ============ layer1 MMA + layer2 MMA fused in registers =============
        {
            float c0[2][4];
            #pragma unroll
            for (int nt=0; nt<2; nt++){
                c0[nt][0]=b1v[nt][0]; c0[nt][1]=b1v[nt][1];
                c0[nt][2]=b1v[nt][0]; c0[nt][3]=b1v[nt][1];
            }
            #pragma unroll
            for (int kt=0; kt<8; kt++){
                uint a0,a1,a2,a3;
                LDSM_X4(a0,a1,a2,a3, haddr + (uint)kt*32u);
                #pragma unroll
                for (int nt=0; nt<2; nt++)
                    MMA_F16(c0[nt], a0,a1,a2,a3, Bq[kt][nt][0], Bq[kt][nt][1]);
            }
            // relu + pack layer1 C directly into layer2 A-fragment
            uint a0 = packh2(fmaxf(c0[0][0],0.f), fmaxf(c0[0][1],0.f));
            uint a1 = packh2(fmaxf(c0[0][2],0.f), fmaxf(c0[0][3],0.f));
            uint a2 = packh2(fmaxf(c0[1][0],0.f), fmaxf(c0[1][1],0.f));
            uint a3 = packh2(fmaxf(c0[1][2],0.f), fmaxf(c0[1][3],0.f));
            float cc[4] = {0.f, 0.f, 0.f, 0.f};
            MMA_F16(cc, a0,a1,a2,a3, B2q[0], B2q[1]);
            // store partial rgb; column XOR-swizzled so both STS and LDS are clean
            const int row = lane >> 2;
            if (m4 < 2){
                *(float2*)&part2[row][warp ^ row][2*m4]           = make_float2(cc[0], cc[1]);
                *(float2*)&part2[row+8][warp ^ row][2*m4]         = make_float2(cc[2], cc[3]);
            }
        }
        __syncthreads();   // B3: part2/wsm visible

        // ============ cross-warp partial sum (lane-parallel) + compositing ====
        {
            const int w2  = lane & 7;
            const int rrp = (lane >> 3) & 1;
            const int s   = warp + 8*rrp;
            float4 p = *(const float4*)&part2[s][w2 ^ (s & 7)][0];
            #pragma unroll
            for (int d=1; d<8; d<<=1){
                p.x += __shfl_xor_sync(0xffffffffu, p.x, d);
                p.y += __shfl_xor_sync(0xffffffffu, p.y, d);
                p.z += __shfl_xor_sync(0xffffffffu, p.z, d);
            }
            if ((lane & 7) == 0 && lane < 16){   // lanes 0 (s0) and 8 (s1)
                float w = wsm[s];
                racc0 = fmaf(w, sigmoidf_(p.x + b2s[0]), racc0);
                racc1 = fmaf(w, sigmoidf_(p.y + b2s[1]), racc1);
                racc2 = fmaf(w, sigmoidf_(p.z + b2s[2]), racc2);
            }
        }
        // next tile's B1 orders all rewrites vs these reads
    }

    // merge lane8's accumulator into lane0, then block reduction
    racc0 += __shfl_down_sync(0xffffffffu, racc0, 8);
    racc1 += __shfl_down_sync(0xffffffffu, racc1, 8);
    racc2 += __shfl_down_sync(0xffffffffu, racc2, 8);
    if (lane == 0){
        accw[warp][0] = racc0; accw[warp][1] = racc1; accw[warp][2] = racc2;
    }
    __syncthreads();
    if (tid < 3){
        float s = alphainv_s;
        #pragma unroll
        for (int w=0; w<8; w++) s += accw[w][tid];
        out[3*r + tid] = s;
    }
}

extern "C" void kernel_launch(void* const* d_in, const int* in_sizes, int n_in,
                              void* d_out, int out_size)
{
    const float* rays_o  = (const float*)d_in[0];
    const float* rays_d  = (const float*)d_in[1];
    const float* density = (const float*)d_in[2];
    const float* k0      = (const float*)d_in[3];
    const float* W0      = (const float*)d_in[4];
    const float* b0      = (const float*)d_in[5];
    const float* W1      = (const float*)d_in[6];
    const float* b1      = (const float*)d_in[7];
    const float* W2      = (const float*)d_in[8];
    const float* b2      = (const float*)d_in[9];
    float* out = (float*)d_out;

    repack_kernel<<<(G3 + 255)/256, 256>>>(density, k0);

    int n_rays = in_sizes[0] / 3;
    dvgo_fused<<<n_rays, 256>>>(rays_o, rays_d,
                                W0, b0, W1, b1, W2, b2, out);
}

// round 14
// speedup vs baseline: 6.7640x; 1.2852x over previous
#include <cuda_runtime.h>
#include <cuda_fp16.h>

#define GRID_N 160
#define G2 (GRID_N*GRID_N)
#define G3 (GRID_N*GRID_N*GRID_N)
#define NS 256
#define SB 32
#define NT (NS/SB)
#define WIDTH 128
#define ACT_SHIFT (-4.59511985013459f)   /* log(1/99) */

typedef unsigned int uint;

#define MMA_F16(C, A0,A1,A2,A3, B0,B1) \
    asm volatile("mma.sync.aligned.m16n8k16.row.col.f32.f16.f16.f32 " \
        "{%0,%1,%2,%3}, {%4,%5,%6,%7}, {%8,%9}, {%0,%1,%2,%3};" \
        : "+f"((C)[0]),"+f"((C)[1]),"+f"((C)[2]),"+f"((C)[3]) \
        : "r"(A0),"r"(A1),"r"(A2),"r"(A3), "r"(B0),"r"(B1))

#define LDSM_X4(R0,R1,R2,R3, ADDR) \
    asm volatile("ldmatrix.sync.aligned.m8n8.x4.shared.b16 {%0,%1,%2,%3}, [%4];" \
        : "=r"(R0),"=r"(R1),"=r"(R2),"=r"(R3) : "r"(ADDR))

__device__ __forceinline__ float sigmoidf_(float x){ return 1.f/(1.f+__expf(-x)); }

__device__ __forceinline__ uint packh2(float a, float b){
    __half2 h = __floats2half2_rn(a, b);
    return *(uint*)&h;
}

// fp16 voxel store: 32B/voxel = 12 half channels (24B) + fp32 sigma (4B) + pad.
__device__ uint4 g_vox[(size_t)G3 * 2];

__global__ __launch_bounds__(256)
void repack_kernel(const float* __restrict__ density, const float* __restrict__ k0)
{
    int v = blockIdx.x * 256 + threadIdx.x;
    if (v >= G3) return;
    uint4 A, B;
    A.x = packh2(k0[0*G3+v],  k0[1*G3+v]);
    A.y = packh2(k0[2*G3+v],  k0[3*G3+v]);
    A.z = packh2(k0[4*G3+v],  k0[5*G3+v]);
    A.w = packh2(k0[6*G3+v],  k0[7*G3+v]);
    B.x = packh2(k0[8*G3+v],  k0[9*G3+v]);
    B.y = packh2(k0[10*G3+v], k0[11*G3+v]);
    B.z = __float_as_uint(density[v]);
    B.w = 0u;
    g_vox[2*(size_t)v]   = A;
    g_vox[2*(size_t)v+1] = B;
}

// unpack one 16B chunk-half: qh=0 -> channels 0..7; qh=1 -> ch 8..11, sigma(fp32), 0,0,0
__device__ __forceinline__ void unp8(uint4 u, int qh, float* f){
    float2 a = __half22float2(*(__half2*)&u.x);
    float2 b = __half22float2(*(__half2*)&u.y);
    f[0]=a.x; f[1]=a.y; f[2]=b.x; f[3]=b.y;
    if (qh == 0){
        float2 c = __half22float2(*(__half2*)&u.z);
        float2 d = __half22float2(*(__half2*)&u.w);
        f[4]=c.x; f[5]=c.y; f[6]=d.x; f[7]=d.y;
    } else {
        f[4]=__uint_as_float(u.z); f[5]=0.f; f[6]=0.f; f[7]=0.f;
    }
}

__global__ __launch_bounds__(256, 3)
void dvgo_fused(const float* __restrict__ rays_o, const float* __restrict__ rays_d,
                const float* __restrict__ W0, const float* __restrict__ b0,
                const float* __restrict__ W1, const float* __restrict__ b1,
                const float* __restrict__ W2, const float* __restrict__ b2,
                float* __restrict__ out)
{
    __shared__ __align__(16) __half fth[SB][16];     // feats fp16 (2 A row-tiles)
    __shared__ __align__(16) __half h0s[SB][136];    // h0 fp16 (2 row-tiles)
    __shared__ __align__(16) float part2[SB][8][4];  // [s][swizzled w][rgb+pad]
    __shared__ float sigs[SB], wsm[SB];
    __shared__ float rts[WIDTH];                     // rayterm per unit
    __shared__ float b2s[3];
    __shared__ float accw[8][3];
    __shared__ float alphainv_s;

    const int r    = blockIdx.x;
    const int tid  = threadIdx.x;
    const int lane = tid & 31;
    const int warp = tid >> 5;       // 0..7 : N-slice (MMA), K-slice (layer2)
    const int j    = tid & 127;
    const int half = tid >> 7;

    if (tid < 3) b2s[tid] = b2[tid];

    const float ox = rays_o[3*r+0], oy = rays_o[3*r+1], oz = rays_o[3*r+2];
    const float dx = rays_d[3*r+0], dy = rays_d[3*r+1], dz = rays_d[3*r+2];

    // ---- per-ray constant: b0 + vemb@W0[12:39]  (exact fp32) ----
    {
        float inv = rsqrtf(dx*dx + dy*dy + dz*dz);
        float vd[3] = {dx*inv, dy*inv, dz*inv};
        float vemb[27];
        vemb[0]=vd[0]; vemb[1]=vd[1]; vemb[2]=vd[2];
        #pragma unroll
        for (int d=0; d<3; d++){
            #pragma unroll
            for (int k=0; k<4; k++){
                float a = vd[d] * (float)(1<<k);
                vemb[3  + d*4 + k] = sinf(a);
                vemb[15 + d*4 + k] = cosf(a);
            }
        }
        float rt = b0[j];
        #pragma unroll
        for (int i=0; i<27; i++)
            rt = fmaf(vemb[i], W0[(12+i)*WIDTH + j], rt);
        if (half == 0) rts[j] = rt;
    }

    const int m4 = lane & 3, ncol = lane >> 2;

    // ---- W1 B-fragments (fp16), warp owns N cols [16w,16w+16) ----
    uint Bq[8][2][2];
    float b1v[2][2];
    #pragma unroll
    for (int nt=0; nt<2; nt++){
        const int n = 16*warp + 8*nt + ncol;
        #pragma unroll
        for (int kt=0; kt<8; kt++){
            #pragma unroll
            for (int p=0; p<2; p++){
                int k = 16*kt + 2*m4 + 8*p;
                Bq[kt][nt][p] = packh2(W1[k*WIDTH + n], W1[(k+1)*WIDTH + n]);
            }
        }
        b1v[nt][0] = b1[16*warp + 8*nt + 2*m4];
        b1v[nt][1] = b1[16*warp + 8*nt + 2*m4 + 1];
    }

    // ---- W0 B-fragments (12 real rows, rows 12..15 zeroed) ----
    uint B0q[2][2];
    #pragma unroll
    for (int nt=0; nt<2; nt++){
        const int n = 16*warp + 8*nt + ncol;
        #pragma unroll
        for (int p=0; p<2; p++){
            int k = 2*m4 + 8*p;
            float wa = (k   < 12) ? W0[k*WIDTH + n]     : 0.f;
            float wb = (k+1 < 12) ? W0[(k+1)*WIDTH + n] : 0.f;
            B0q[nt][p] = packh2(wa, wb);
        }
    }

    // ---- W2 B-fragment: K-slice rows [16w,16w+16), N=8 (cols 0..2 real) ----
    uint B2q[2];
    #pragma unroll
    for (int p=0; p<2; p++){
        int k = 16*warp + 2*m4 + 8*p;
        float wa = (ncol < 3) ? W2[k*3 + ncol]     : 0.f;
        float wb = (ncol < 3) ? W2[(k+1)*3 + ncol] : 0.f;
        B2q[p] = packh2(wa, wb);
    }

    __syncthreads();
    float rt0[2], rt1[2];
    #pragma unroll
    for (int nt=0; nt<2; nt++){
        rt0[nt] = rts[16*warp + 8*nt + 2*m4];
        rt1[nt] = rts[16*warp + 8*nt + 2*m4 + 1];
    }

    // ldmatrix base addresses (row-tile g adds g*512 for fth, g*4352 for h0s)
    const uint faddr = (uint)__cvta_generic_to_shared(&fth[lane & 15][0]) + (uint)(lane >> 4)*16u;
    const uint haddr = (uint)__cvta_generic_to_shared(&h0s[lane & 15][0]) + (uint)(lane >> 4)*16u;

    // sampling lane decomposition: lane = ss(2)|xy(2)|qh(1); 1 sample per thread
    const int ss  = lane >> 3;
    const int xy  = (lane >> 1) & 3;
    const int qh  = lane & 1;
    const int cxk = xy & 1, cyk = xy >> 1;
    const int smp = warp + 8*ss;        // this thread's sample within tile
    const char* gvb = (const char*)g_vox;

    float T = 1.f;
    float racc0=0.f, racc1=0.f, racc2=0.f;

    // ---- prefetch tile 0 gathers (both z corners, 16B chunk-half) ----
    uint4 pu0, pu1; float pwxy, paz;
    {
        float t = 0.2f + (float)(smp) * (1.6f/255.0f);
        float gx = fminf(fmaxf((fmaf(dx,t,ox)+1.f)*79.5f, 0.f), 159.f);
        float gy = fminf(fmaxf((fmaf(dy,t,oy)+1.f)*79.5f, 0.f), 159.f);
        float gz = fminf(fmaxf((fmaf(dz,t,oz)+1.f)*79.5f, 0.f), 159.f);
        int x0 = min((int)gx, 158), y0 = min((int)gy, 158), z0 = min((int)gz, 158);
        float ax = gx-(float)x0, ay = gy-(float)y0;
        paz = gz-(float)z0;
        uint off = (uint)(((x0+cxk)*GRID_N + (y0+cyk))*GRID_N + z0) * 32u + (uint)qh*16u;
        pu0 = __ldg((const uint4*)(gvb + off));
        pu1 = __ldg((const uint4*)(gvb + off + 32u));
        pwxy = (cxk ? ax : 1.f-ax) * (cyk ? ay : 1.f-ay);
    }

    for (int tt=0; tt<NT; tt++){
        // ====== consume prefetched gathers: unpack, z-lerp, xy-reduce =========
        {
            float f0[8], f1[8], v[8];
            unp8(pu0, qh, f0);
            unp8(pu1, qh, f1);
            #pragma unroll
            for (int i=0; i<8; i++)
                v[i] = fmaf(paz, f1[i]-f0[i], f0[i]) * pwxy;
            #pragma unroll
            for (int d=2; d<=4; d<<=1){
                #pragma unroll
                for (int i=0; i<8; i++)
                    v[i] += __shfl_xor_sync(0xffffffffu, v[i], d);
            }
            if (xy == 0){
                *(uint4*)&fth[smp][8*qh] = make_uint4(
                    packh2(v[0],v[1]), packh2(v[2],v[3]),
                    packh2(v[4],v[5]), packh2(v[6],v[7]));
                if (qh == 1) sigs[smp] = v[4];   // sigma (exact fp32)
            }
        }
        // ====== prefetch next tile (latency hides behind layer0+layer1) ======
        if (tt+1 < NT){
            float t = 0.2f + (float)((tt+1)*SB + smp) * (1.6f/255.0f);
            float gx = fminf(fmaxf((fmaf(dx,t,ox)+1.f)*79.5f, 0.f), 159.f);
            float gy = fminf(fmaxf((fmaf(dy,t,oy)+1.f)*79.5f, 0.f), 159.f);
            float gz = fminf(fmaxf((fmaf(dz,t,oz)+1.f)*79.5f, 0.f), 159.f);
            int x0 = min((int)gx, 158), y0 = min((int)gy, 158), z0 = min((int)gz, 158);
            float ax = gx-(float)x0, ay = gy-(float)y0;
            paz = gz-(float)z0;
            uint off = (uint)(((x0+cxk)*GRID_N + (y0+cyk))*GRID_N + z0) * 32u + (uint)qh*16u;
            pu0 = __ldg((const uint4*)(gvb + off));
            pu1 = __ldg((const uint4*)(gvb + off + 32u));
            pwxy = (cxk ? ax : 1.f-ax) * (cyk ? ay : 1.f-ay);
        }
        __syncthreads();   // B1: fth/sigs visible

        // ============ transmittance (warp 0): full-warp log/exp scan ==========
        if (warp == 0){
            float e  = __expf(sigs[lane] + ACT_SHIFT);
            float a  = 1.f - rsqrtf(1.f + e);
            float lg = __logf(1.f - a + 1e-10f);
            float sc = lg;
            #pragma unroll
            for (int d=1; d<32; d<<=1){
                float n = __shfl_up_sync(0xffffffffu, sc, d);
                if (lane >= d) sc += n;
            }
            wsm[lane] = a * T * __expf(sc - lg);     // exclusive prefix
            T *= __expf(__shfl_sync(0xffffffffu, sc, 31));
            if (tt == NT-1 && lane == 0) alphainv_s = T;
        }

        // ============ layer0: fp16 MMA per row-tile, rayterm as C init ========
        #pragma unroll
        for (int g=0; g<2; g++){
            float c[2][4];
            #pragma unroll
            for (int nt=0; nt<2; nt++){
                c[nt][0]=rt0[nt]; c[nt][1]=rt1[nt];
                c[nt][2]=rt0[nt]; c[nt][3]=rt1[nt];
            }
            uint a0,a1,a2,a3;
            LDSM_X4(a0,a1,a2,a3, faddr + (uint)g*512u);
            #pragma unroll
            for (int nt=0; nt<2; nt++)
                MMA_F16(c[nt], a0,a1,a2,a3, B0q[nt][0], B0q[nt][1]);
            const int row = lane >> 2;
            #pragma unroll
            for (int nt=0; nt<2; nt++){
                const int n0 = 16*warp + 8*nt + 2*m4;
                *(uint*)&h0s[16*g + row][n0]     = packh2(fmaxf(c[nt][0],0.f), fmaxf(c[nt][1],0.f));
                *(uint*)&h0s[16*g + row + 8][n0] = packh2(fmaxf(c[nt][2],0.f), fmaxf(c[nt][3],0.f));
            }
        }
        __syncthreads();   // B2: h0s visible

        // ============ layer1 MMA + layer2 MMA fused, per row-tile =============
        #pragma unroll
        for (int g=0; g<2; g++){
            float c0[2][4];
            #pragma unroll
            for (int nt=0; nt<2; nt++){
                c0[nt][0]=b1v[nt][0]; c0[nt][1]=b1v[nt][1];
                c0[nt][2]=b1v[nt][0]; c0[nt][3]=b1v[nt][1];
            }
            #pragma unroll
            for (int kt=0; kt<8; kt++){
                uint a0,a1,a2,a3;
                LDSM_X4(a0,a1,a2,a3, haddr + (uint)g*4352u + (uint)kt*32u);
                #pragma unroll
                for (int nt=0; nt<2; nt++)
                    MMA_F16(c0[nt], a0,a1,a2,a3, Bq[kt][nt][0], Bq[kt][nt][1]);
            }
            // relu + pack layer1 C directly into layer2 A-fragment
            uint a0 = packh2(fmaxf(c0[0][0],0.f), fmaxf(c0[0][1],0.f));
            uint a1 = packh2(fmaxf(c0[0][2],0.f), fmaxf(c0[0][3],0.f));
            uint a2 = packh2(fmaxf(c0[1][0],0.f), fmaxf(c0[1][1],0.f));
            uint a3 = packh2(fmaxf(c0[1][2],0.f), fmaxf(c0[1][3],0.f));
            float cc[4] = {0.f, 0.f, 0.f, 0.f};
            MMA_F16(cc, a0,a1,a2,a3, B2q[0], B2q[1]);
            const int row = lane >> 2;
            if (m4 < 2){
                *(float2*)&part2[16*g + row][warp ^ row][2*m4]     = make_float2(cc[0], cc[1]);
                *(float2*)&part2[16*g + row + 8][warp ^ row][2*m4] = make_float2(cc[2], cc[3]);
            }
        }
        __syncthreads();   // B3: part2/wsm visible

        // ============ cross-warp partial sum (lane-parallel) + compositing ====
        {
            const int w2 = lane & 7;
            const int s  = warp + 8*(lane >> 3);
            float4 p = *(const float4*)&part2[s][w2 ^ (s & 7)][0];
            #pragma unroll
            for (int d=1; d<8; d<<=1){
                p.x += __shfl_xor_sync(0xffffffffu, p.x, d);
                p.y += __shfl_xor_sync(0xffffffffu, p.y, d);
                p.z += __shfl_xor_sync(0xffffffffu, p.z, d);
            }
            if (w2 == 0){       // lanes 0,8,16,24 own samples warp+0,8,16,24
                float w = wsm[s];
                racc0 = fmaf(w, sigmoidf_(p.x + b2s[0]), racc0);
                racc1 = fmaf(w, sigmoidf_(p.y + b2s[1]), racc1);
                racc2 = fmaf(w, sigmoidf_(p.z + b2s[2]), racc2);
            }
        }
        // next tile's B1 orders all rewrites vs these reads
    }

    // merge accumulator lanes 8,16,24 into lane 0, then block reduction
    racc0 += __shfl_down_sync(0xffffffffu, racc0, 16);
    racc1 += __shfl_down_sync(0xffffffffu, racc1, 16);
    racc2 += __shfl_down_sync(0xffffffffu, racc2, 16);
    racc0 += __shfl_down_sync(0xffffffffu, racc0, 8);
    racc1 += __shfl_down_sync(0xffffffffu, racc1, 8);
    racc2 += __shfl_down_sync(0xffffffffu, racc2, 8);
    if (lane == 0){
        accw[warp][0] = racc0; accw[warp][1] = racc1; accw[warp][2] = racc2;
    }
    __syncthreads();
    if (tid < 3){
        float s = alphainv_s;
        #pragma unroll
        for (int w=0; w<8; w++) s += accw[w][tid];
        out[3*r + tid] = s;
    }
}

extern "C" void kernel_launch(void* const* d_in, const int* in_sizes, int n_in,
                              void* d_out, int out_size)
{
    const float* rays_o  = (const float*)d_in[0];
    const float* rays_d  = (const float*)d_in[1];
    const float* density = (const float*)d_in[2];
    const float* k0      = (const float*)d_in[3];
    const float* W0      = (const float*)d_in[4];
    const float* b0      = (const float*)d_in[5];
    const float* W1      = (const float*)d_in[6];
    const float* b1      = (const float*)d_in[7];
    const float* W2      = (const float*)d_in[8];
    const float* b2      = (const float*)d_in[9];
    float* out = (float*)d_out;

    repack_kernel<<<(G3 + 255)/256, 256>>>(density, k0);

    int n_rays = in_sizes[0] / 3;
    dvgo_fused<<<n_rays, 256>>>(rays_o, rays_d,
                                W0, b0, W1, b1, W2, b2, out);
}

// round 15
// speedup vs baseline: 6.9857x; 1.0328x over previous
#include <cuda_runtime.h>
#include <cuda_fp16.h>

#define GRID_N 160
#define G2 (GRID_N*GRID_N)
#define G3 (GRID_N*GRID_N*GRID_N)
#define NS 256
#define SB 32
#define NT (NS/SB)
#define WIDTH 128
#define ACT_SHIFT (-4.59511985013459f)   /* log(1/99) */

typedef unsigned int uint;

#define MMA_F16(C, A0,A1,A2,A3, B0,B1) \
    asm volatile("mma.sync.aligned.m16n8k16.row.col.f32.f16.f16.f32 " \
        "{%0,%1,%2,%3}, {%4,%5,%6,%7}, {%8,%9}, {%0,%1,%2,%3};" \
        : "+f"((C)[0]),"+f"((C)[1]),"+f"((C)[2]),"+f"((C)[3]) \
        : "r"(A0),"r"(A1),"r"(A2),"r"(A3), "r"(B0),"r"(B1))

#define LDSM_X4(R0,R1,R2,R3, ADDR) \
    asm volatile("ldmatrix.sync.aligned.m8n8.x4.shared.b16 {%0,%1,%2,%3}, [%4];" \
        : "=r"(R0),"=r"(R1),"=r"(R2),"=r"(R3) : "r"(ADDR))

__device__ __forceinline__ float sigmoidf_(float x){ return 1.f/(1.f+__expf(-x)); }

__device__ __forceinline__ uint packh2(float a, float b){
    __half2 h = __floats2half2_rn(a, b);
    return *(uint*)&h;
}
// packed fp16 lerp+weight: ((b-a)*az + a) * wxy
__device__ __forceinline__ uint h2lerpw(uint a, uint b, uint az, uint wxy){
    __half2 A = *(__half2*)&a, B = *(__half2*)&b;
    __half2 v = __hmul2(__hfma2(*(__half2*)&az, __hsub2(B, A), A), *(__half2*)&wxy);
    return *(uint*)&v;
}
__device__ __forceinline__ uint h2add(uint a, uint b){
    __half2 v = __hadd2(*(__half2*)&a, *(__half2*)&b);
    return *(uint*)&v;
}

// fp16 voxel store: 32B/voxel = 12 half channels (24B) + fp32 sigma (4B) + pad.
__device__ uint4 g_vox[(size_t)G3 * 2];

__global__ __launch_bounds__(256)
void repack_kernel(const float* __restrict__ density, const float* __restrict__ k0)
{
    int v = blockIdx.x * 256 + threadIdx.x;
    if (v >= G3) return;
    uint4 A, B;
    A.x = packh2(k0[0*G3+v],  k0[1*G3+v]);
    A.y = packh2(k0[2*G3+v],  k0[3*G3+v]);
    A.z = packh2(k0[4*G3+v],  k0[5*G3+v]);
    A.w = packh2(k0[6*G3+v],  k0[7*G3+v]);
    B.x = packh2(k0[8*G3+v],  k0[9*G3+v]);
    B.y = packh2(k0[10*G3+v], k0[11*G3+v]);
    B.z = __float_as_uint(density[v]);
    B.w = 0u;
    g_vox[2*(size_t)v]   = A;
    g_vox[2*(size_t)v+1] = B;
}

__global__ __launch_bounds__(256, 3)
void dvgo_fused(const float* __restrict__ rays_o, const float* __restrict__ rays_d,
                const float* __restrict__ W0, const float* __restrict__ b0,
                const float* __restrict__ W1, const float* __restrict__ b1,
                const float* __restrict__ W2, const float* __restrict__ b2,
                float* __restrict__ out)
{
    __shared__ __align__(16) __half fth[SB][16];     // feats fp16 (2 A row-tiles)
    __shared__ __align__(16) __half h0s[SB][136];    // h0 fp16 (2 row-tiles)
    __shared__ __align__(16) float part2[SB][8][4];  // [s][swizzled w][rgb+pad]
    __shared__ float sigs[SB], wsm[2][SB];
    __shared__ float rts[WIDTH];                     // rayterm per unit
    __shared__ float b2s[3];
    __shared__ float accw[8][3];
    __shared__ float alphainv_s;

    const int r    = blockIdx.x;
    const int tid  = threadIdx.x;
    const int lane = tid & 31;
    const int warp = tid >> 5;       // 0..7 : N-slice (MMA), K-slice (layer2)
    const int j    = tid & 127;
    const int half = tid >> 7;

    if (tid < 3) b2s[tid] = b2[tid];

    const float ox = rays_o[3*r+0], oy = rays_o[3*r+1], oz = rays_o[3*r+2];
    const float dx = rays_d[3*r+0], dy = rays_d[3*r+1], dz = rays_d[3*r+2];

    // ---- per-ray constant: b0 + vemb@W0[12:39]  (exact fp32) ----
    {
        float inv = rsqrtf(dx*dx + dy*dy + dz*dz);
        float vd[3] = {dx*inv, dy*inv, dz*inv};
        float vemb[27];
        vemb[0]=vd[0]; vemb[1]=vd[1]; vemb[2]=vd[2];
        #pragma unroll
        for (int d=0; d<3; d++){
            #pragma unroll
            for (int k=0; k<4; k++){
                float a = vd[d] * (float)(1<<k);
                vemb[3  + d*4 + k] = sinf(a);
                vemb[15 + d*4 + k] = cosf(a);
            }
        }
        float rt = b0[j];
        #pragma unroll
        for (int i=0; i<27; i++)
            rt = fmaf(vemb[i], W0[(12+i)*WIDTH + j], rt);
        if (half == 0) rts[j] = rt;
    }

    const int m4 = lane & 3, ncol = lane >> 2;

    // ---- W1 B-fragments (fp16), warp owns N cols [16w,16w+16) ----
    uint Bq[8][2][2];
    float b1v[2][2];
    #pragma unroll
    for (int nt=0; nt<2; nt++){
        const int n = 16*warp + 8*nt + ncol;
        #pragma unroll
        for (int kt=0; kt<8; kt++){
            #pragma unroll
            for (int p=0; p<2; p++){
                int k = 16*kt + 2*m4 + 8*p;
                Bq[kt][nt][p] = packh2(W1[k*WIDTH + n], W1[(k+1)*WIDTH + n]);
            }
        }
        b1v[nt][0] = b1[16*warp + 8*nt + 2*m4];
        b1v[nt][1] = b1[16*warp + 8*nt + 2*m4 + 1];
    }

    // ---- W0 B-fragments (12 real rows, rows 12..15 zeroed) ----
    uint B0q[2][2];
    #pragma unroll
    for (int nt=0; nt<2; nt++){
        const int n = 16*warp + 8*nt + ncol;
        #pragma unroll
        for (int p=0; p<2; p++){
            int k = 2*m4 + 8*p;
            float wa = (k   < 12) ? W0[k*WIDTH + n]     : 0.f;
            float wb = (k+1 < 12) ? W0[(k+1)*WIDTH + n] : 0.f;
            B0q[nt][p] = packh2(wa, wb);
        }
    }

    // ---- W2 B-fragment: K-slice rows [16w,16w+16), N=8 (cols 0..2 real) ----
    uint B2q[2];
    #pragma unroll
    for (int p=0; p<2; p++){
        int k = 16*warp + 2*m4 + 8*p;
        float wa = (ncol < 3) ? W2[k*3 + ncol]     : 0.f;
        float wb = (ncol < 3) ? W2[(k+1)*3 + ncol] : 0.f;
        B2q[p] = packh2(wa, wb);
    }

    __syncthreads();
    float rt0[2], rt1[2];
    #pragma unroll
    for (int nt=0; nt<2; nt++){
        rt0[nt] = rts[16*warp + 8*nt + 2*m4];
        rt1[nt] = rts[16*warp + 8*nt + 2*m4 + 1];
    }

    // ldmatrix base addresses (row-tile g adds g*512 for fth, g*4352 for h0s)
    const uint faddr = (uint)__cvta_generic_to_shared(&fth[lane & 15][0]) + (uint)(lane >> 4)*16u;
    const uint haddr = (uint)__cvta_generic_to_shared(&h0s[lane & 15][0]) + (uint)(lane >> 4)*16u;

    // sampling lane decomposition: lane = ss(2)|xy(2)|qh(1); 1 sample per thread
    const int ss  = lane >> 3;
    const int xy  = (lane >> 1) & 3;
    const int qh  = lane & 1;
    const int cxk = xy & 1, cyk = xy >> 1;
    const int smp = warp + 8*ss;        // this thread's sample within tile
    const char* gvb = (const char*)g_vox;

    float T = 1.f;
    float racc0=0.f, racc1=0.f, racc2=0.f;

    // ---- prefetch tile 0 gathers (both z corners, 16B chunk-half) ----
    uint4 pu0, pu1; float pwxy, paz;
    {
        float t = 0.2f + (float)(smp) * (1.6f/255.0f);
        float gx = fminf(fmaxf((fmaf(dx,t,ox)+1.f)*79.5f, 0.f), 159.f);
        float gy = fminf(fmaxf((fmaf(dy,t,oy)+1.f)*79.5f, 0.f), 159.f);
        float gz = fminf(fmaxf((fmaf(dz,t,oz)+1.f)*79.5f, 0.f), 159.f);
        int x0 = min((int)gx, 158), y0 = min((int)gy, 158), z0 = min((int)gz, 158);
        float ax = gx-(float)x0, ay = gy-(float)y0;
        paz = gz-(float)z0;
        uint off = (uint)(((x0+cxk)*GRID_N + (y0+cyk))*GRID_N + z0) * 32u + (uint)qh*16u;
        pu0 = __ldg((const uint4*)(gvb + off));
        pu1 = __ldg((const uint4*)(gvb + off + 32u));
        pwxy = (cxk ? ax : 1.f-ax) * (cyk ? ay : 1.f-ay);
    }

    for (int tt=0; tt<NT; tt++){
        // ====== consume prefetched gathers: fp16x2 lerp + xy-reduce ===========
        {
            uint haz  = packh2(paz,  paz);
            uint hwxy = packh2(pwxy, pwxy);
            uint4 u0 = pu0, u1 = pu1;
            float s0v = 0.f, s1v = 0.f;
            if (qh){  // extract fp32 sigma, zero non-half payload
                s0v = __uint_as_float(u0.z);  s1v = __uint_as_float(u1.z);
                u0.z = 0u; u0.w = 0u; u1.z = 0u; u1.w = 0u;
            }
            uint v0 = h2lerpw(u0.x, u1.x, haz, hwxy);
            uint v1 = h2lerpw(u0.y, u1.y, haz, hwxy);
            uint v2 = h2lerpw(u0.z, u1.z, haz, hwxy);
            uint v3 = h2lerpw(u0.w, u1.w, haz, hwxy);
            float sg = fmaf(paz, s1v - s0v, s0v) * pwxy;
            #pragma unroll
            for (int d=2; d<=4; d<<=1){
                v0 = h2add(v0, __shfl_xor_sync(0xffffffffu, v0, d));
                v1 = h2add(v1, __shfl_xor_sync(0xffffffffu, v1, d));
                v2 = h2add(v2, __shfl_xor_sync(0xffffffffu, v2, d));
                v3 = h2add(v3, __shfl_xor_sync(0xffffffffu, v3, d));
                sg += __shfl_xor_sync(0xffffffffu, sg, d);
            }
            if (xy == 0){
                *(uint4*)&fth[smp][8*qh] = make_uint4(v0, v1, v2, v3);
                if (qh) sigs[smp] = sg;          // sigma (exact fp32)
            }
        }
        // ====== prefetch next tile (latency hides behind layer0+layer1) ======
        if (tt+1 < NT){
            float t = 0.2f + (float)((tt+1)*SB + smp) * (1.6f/255.0f);
            float gx = fminf(fmaxf((fmaf(dx,t,ox)+1.f)*79.5f, 0.f), 159.f);
            float gy = fminf(fmaxf((fmaf(dy,t,oy)+1.f)*79.5f, 0.f), 159.f);
            float gz = fminf(fmaxf((fmaf(dz,t,oz)+1.f)*79.5f, 0.f), 159.f);
            int x0 = min((int)gx, 158), y0 = min((int)gy, 158), z0 = min((int)gz, 158);
            float ax = gx-(float)x0, ay = gy-(float)y0;
            paz = gz-(float)z0;
            uint off = (uint)(((x0+cxk)*GRID_N + (y0+cyk))*GRID_N + z0) * 32u + (uint)qh*16u;
            pu0 = __ldg((const uint4*)(gvb + off));
            pu1 = __ldg((const uint4*)(gvb + off + 32u));
            pwxy = (cxk ? ax : 1.f-ax) * (cyk ? ay : 1.f-ay);
        }
        __syncthreads();   // B1: fth/sigs of tile tt AND part2 of tile tt-1 visible

        // ============ deferred compositing of tile tt-1 ======================
        if (tt > 0){
            const int w2 = lane & 7;
            const int s  = warp + 8*(lane >> 3);
            float4 p = *(const float4*)&part2[s][w2 ^ (s & 7)][0];
            #pragma unroll
            for (int d=1; d<8; d<<=1){
                p.x += __shfl_xor_sync(0xffffffffu, p.x, d);
                p.y += __shfl_xor_sync(0xffffffffu, p.y, d);
                p.z += __shfl_xor_sync(0xffffffffu, p.z, d);
            }
            if (w2 == 0){
                float w = wsm[(tt-1)&1][s];
                racc0 = fmaf(w, sigmoidf_(p.x + b2s[0]), racc0);
                racc1 = fmaf(w, sigmoidf_(p.y + b2s[1]), racc1);
                racc2 = fmaf(w, sigmoidf_(p.z + b2s[2]), racc2);
            }
        }

        // ============ transmittance (warp 0): full-warp log/exp scan ==========
        if (warp == 0){
            float e  = __expf(sigs[lane] + ACT_SHIFT);
            float a  = 1.f - rsqrtf(1.f + e);
            float lg = __logf(1.f - a + 1e-10f);
            float sc = lg;
            #pragma unroll
            for (int d=1; d<32; d<<=1){
                float n = __shfl_up_sync(0xffffffffu, sc, d);
                if (lane >= d) sc += n;
            }
            wsm[tt&1][lane] = a * T * __expf(sc - lg);   // exclusive prefix
            T *= __expf(__shfl_sync(0xffffffffu, sc, 31));
            if (tt == NT-1 && lane == 0) alphainv_s = T;
        }

        // ============ layer0: fp16 MMA per row-tile, rayterm as C init ========
        #pragma unroll
        for (int g=0; g<2; g++){
            float c[2][4];
            #pragma unroll
            for (int nt=0; nt<2; nt++){
                c[nt][0]=rt0[nt]; c[nt][1]=rt1[nt];
                c[nt][2]=rt0[nt]; c[nt][3]=rt1[nt];
            }
            uint a0,a1,a2,a3;
            LDSM_X4(a0,a1,a2,a3, faddr + (uint)g*512u);
            #pragma unroll
            for (int nt=0; nt<2; nt++)
                MMA_F16(c[nt], a0,a1,a2,a3, B0q[nt][0], B0q[nt][1]);
            const int row = lane >> 2;
            #pragma unroll
            for (int nt=0; nt<2; nt++){
                const int n0 = 16*warp + 8*nt + 2*m4;
                *(uint*)&h0s[16*g + row][n0]     = packh2(fmaxf(c[nt][0],0.f), fmaxf(c[nt][1],0.f));
                *(uint*)&h0s[16*g + row + 8][n0] = packh2(fmaxf(c[nt][2],0.f), fmaxf(c[nt][3],0.f));
            }
        }
        __syncthreads();   // B2: h0s visible

        // ============ layer1 MMA + layer2 MMA fused, per row-tile =============
        #pragma unroll
        for (int g=0; g<2; g++){
            float c0[2][4];
            #pragma unroll
            for (int nt=0; nt<2; nt++){
                c0[nt][0]=b1v[nt][0]; c0[nt][1]=b1v[nt][1];
                c0[nt][2]=b1v[nt][0]; c0[nt][3]=b1v[nt][1];
            }
            #pragma unroll
            for (int kt=0; kt<8; kt++){
                uint a0,a1,a2,a3;
                LDSM_X4(a0,a1,a2,a3, haddr + (uint)g*4352u + (uint)kt*32u);
                #pragma unroll
                for (int nt=0; nt<2; nt++)
                    MMA_F16(c0[nt], a0,a1,a2,a3, Bq[kt][nt][0], Bq[kt][nt][1]);
            }
            // relu + pack layer1 C directly into layer2 A-fragment
            uint a0 = packh2(fmaxf(c0[0][0],0.f), fmaxf(c0[0][1],0.f));
            uint a1 = packh2(fmaxf(c0[0][2],0.f), fmaxf(c0[0][3],0.f));
            uint a2 = packh2(fmaxf(c0[1][0],0.f), fmaxf(c0[1][1],0.f));
            uint a3 = packh2(fmaxf(c0[1][2],0.f), fmaxf(c0[1][3],0.f));
            float cc[4] = {0.f, 0.f, 0.f, 0.f};
            MMA_F16(cc, a0,a1,a2,a3, B2q[0], B2q[1]);
            const int row = lane >> 2;
            if (m4 < 2){
                *(float2*)&part2[16*g + row][warp ^ row][2*m4]     = make_float2(cc[0], cc[1]);
                *(float2*)&part2[16*g + row + 8][warp ^ row][2*m4] = make_float2(cc[2], cc[3]);
            }
        }
        // no B3: next tile's B1 orders part2 writes before the deferred composite
    }

    __syncthreads();   // final: part2 of tile NT-1 visible
    {
        const int w2 = lane & 7;
        const int s  = warp + 8*(lane >> 3);
        float4 p = *(const float4*)&part2[s][w2 ^ (s & 7)][0];
        #pragma unroll
        for (int d=1; d<8; d<<=1){
            p.x += __shfl_xor_sync(0xffffffffu, p.x, d);
            p.y += __shfl_xor_sync(0xffffffffu, p.y, d);
            p.z += __shfl_xor_sync(0xffffffffu, p.z, d);
        }
        if (w2 == 0){
            float w = wsm[(NT-1)&1][s];
            racc0 = fmaf(w, sigmoidf_(p.x + b2s[0]), racc0);
            racc1 = fmaf(w, sigmoidf_(p.y + b2s[1]), racc1);
            racc2 = fmaf(w, sigmoidf_(p.z + b2s[2]), racc2);
        }
    }

    // merge accumulator lanes 8,16,24 into lane 0, then block reduction
    racc0 += __shfl_down_sync(0xffffffffu, racc0, 16);
    racc1 += __shfl_down_sync(0xffffffffu, racc1, 16);
    racc2 += __shfl_down_sync(0xffffffffu, racc2, 16);
    racc0 += __shfl_down_sync(0xffffffffu, racc0, 8);
    racc1 += __shfl_down_sync(0xffffffffu, racc1, 8);
    racc2 += __shfl_down_sync(0xffffffffu, racc2, 8);
    if (lane == 0){
        accw[warp][0] = racc0; accw[warp][1] = racc1; accw[warp][2] = racc2;
    }
    __syncthreads();
    if (tid < 3){
        float s = alphainv_s;
        #pragma unroll
        for (int w=0; w<8; w++) s += accw[w][tid];
        out[3*r + tid] = s;
    }
}

extern "C" void kernel_launch(void* const* d_in, const int* in_sizes, int n_in,
                              void* d_out, int out_size)
{
    const float* rays_o  = (const float*)d_in[0];
    const float* rays_d  = (const float*)d_in[1];
    const float* density = (const float*)d_in[2];
    const float* k0      = (const float*)d_in[3];
    const float* W0      = (const float*)d_in[4];
    const float* b0      = (const float*)d_in[5];
    const float* W1      = (const float*)d_in[6];
    const float* b1      = (const float*)d_in[7];
    const float* W2      = (const float*)d_in[8];
    const float* b2      = (const float*)d_in[9];
    float* out = (float*)d_out;

    repack_kernel<<<(G3 + 255)/256, 256>>>(density, k0);

    int n_rays = in_sizes[0] / 3;
    dvgo_fused<<<n_rays, 256>>>(rays_o, rays_d,
                                W0, b0, W1, b1, W2, b2, out);
}